// round 1
// baseline (speedup 1.0000x reference)
#include <cuda_runtime.h>
#include <math.h>

#define D_MODEL 1024
#define NH      16
#define DK      64
#define BATCH   2
#define SEQ     2048
#define M_TOT   (BATCH * SEQ)   // 4096

// ---------------- scratch (static device memory; no allocations) ----------------
__device__ float g_q[M_TOT * D_MODEL];
__device__ float g_k[M_TOT * D_MODEL];
__device__ float g_v[M_TOT * D_MODEL];
__device__ float g_ctx[M_TOT * D_MODEL];

// ---------------- packed f32x2 helpers (Blackwell FFMA2 path) ----------------
static __device__ __forceinline__ unsigned long long f2_pack(float x, float y) {
    unsigned long long r;
    asm("mov.b64 %0, {%1, %2};" : "=l"(r) : "f"(x), "f"(y));
    return r;
}
static __device__ __forceinline__ unsigned long long f2_fma(unsigned long long a,
                                                            unsigned long long b,
                                                            unsigned long long c) {
    unsigned long long r;
    asm("fma.rn.f32x2 %0, %1, %2, %3;" : "=l"(r) : "l"(a), "l"(b), "l"(c));
    return r;
}
static __device__ __forceinline__ unsigned long long f2_mul(unsigned long long a,
                                                            unsigned long long b) {
    unsigned long long r;
    asm("mul.rn.f32x2 %0, %1, %2;" : "=l"(r) : "l"(a), "l"(b));
    return r;
}
static __device__ __forceinline__ float2 f2_unpack(unsigned long long v) {
    float2 f;
    asm("mov.b64 {%0, %1}, %2;" : "=f"(f.x), "=f"(f.y) : "l"(v));
    return f;
}

// ---------------- SGEMM: C[M,N] = A[M,K] * W[N,K]^T  (M=4096, N=K=1024) ------
// 128x128 block tile, BK=8, 256 threads, 8x8 per-thread microtile, f32x2 FMAs.
__device__ __forceinline__ void gemm_body(const float* __restrict__ A,
                                          const float* __restrict__ W,
                                          float* __restrict__ C) {
    constexpr int K = D_MODEL;
    constexpr int N = D_MODEL;
    __shared__ float As[8][128];
    __shared__ float Bs[8][128];

    const int m0 = blockIdx.y * 128;
    const int n0 = blockIdx.x * 128;
    const int tid = threadIdx.x;
    const int tx = tid & 15;         // 0..15 (cols)
    const int ty = tid >> 4;         // 0..15 (rows)
    const int lr = tid >> 1;         // 0..127 load row
    const int lk = (tid & 1) << 2;   // 0 or 4

    const float* Ag = A + (size_t)(m0 + lr) * K + lk;
    const float* Wg = W + (size_t)(n0 + lr) * K + lk;

    unsigned long long acc[8][4];
#pragma unroll
    for (int i = 0; i < 8; i++)
#pragma unroll
        for (int j = 0; j < 4; j++) acc[i][j] = 0ull;

    float4 av = *(const float4*)(Ag);
    float4 wv = *(const float4*)(Wg);

    for (int k0 = 0; k0 < K; k0 += 8) {
        As[lk + 0][lr] = av.x; As[lk + 1][lr] = av.y;
        As[lk + 2][lr] = av.z; As[lk + 3][lr] = av.w;
        Bs[lk + 0][lr] = wv.x; Bs[lk + 1][lr] = wv.y;
        Bs[lk + 2][lr] = wv.z; Bs[lk + 3][lr] = wv.w;
        __syncthreads();

        if (k0 + 8 < K) {   // prefetch next K-slice while computing
            av = *(const float4*)(Ag + k0 + 8);
            wv = *(const float4*)(Wg + k0 + 8);
        }

#pragma unroll
        for (int kk = 0; kk < 8; kk++) {
            const float* ap = &As[kk][ty * 8];
            const float* bp = &Bs[kk][tx * 8];
            unsigned long long b0 = *(const unsigned long long*)(bp);
            unsigned long long b1 = *(const unsigned long long*)(bp + 2);
            unsigned long long b2 = *(const unsigned long long*)(bp + 4);
            unsigned long long b3 = *(const unsigned long long*)(bp + 6);
            float4 a0 = *(const float4*)(ap);
            float4 a1 = *(const float4*)(ap + 4);
            float a[8] = {a0.x, a0.y, a0.z, a0.w, a1.x, a1.y, a1.z, a1.w};
#pragma unroll
            for (int i = 0; i < 8; i++) {
                unsigned long long aa = f2_pack(a[i], a[i]);
                acc[i][0] = f2_fma(aa, b0, acc[i][0]);
                acc[i][1] = f2_fma(aa, b1, acc[i][1]);
                acc[i][2] = f2_fma(aa, b2, acc[i][2]);
                acc[i][3] = f2_fma(aa, b3, acc[i][3]);
            }
        }
        __syncthreads();
    }

#pragma unroll
    for (int i = 0; i < 8; i++) {
        float* Cp = C + (size_t)(m0 + ty * 8 + i) * N + n0 + tx * 8;
        float2 c0 = f2_unpack(acc[i][0]);
        float2 c1 = f2_unpack(acc[i][1]);
        float2 c2 = f2_unpack(acc[i][2]);
        float2 c3 = f2_unpack(acc[i][3]);
        *(float4*)Cp       = make_float4(c0.x, c0.y, c1.x, c1.y);
        *(float4*)(Cp + 4) = make_float4(c2.x, c2.y, c3.x, c3.y);
    }
}

__global__ void __launch_bounds__(256) qkv_gemm(const float* __restrict__ x,
                                                const float* __restrict__ Wq,
                                                const float* __restrict__ Wk,
                                                const float* __restrict__ Wv) {
    const float* W = (blockIdx.z == 0) ? Wq : (blockIdx.z == 1) ? Wk : Wv;
    float* C = (blockIdx.z == 0) ? g_q : (blockIdx.z == 1) ? g_k : g_v;
    gemm_body(x, W, C);
}

__global__ void __launch_bounds__(256) out_gemm(const float* __restrict__ Wo,
                                                float* __restrict__ C) {
    gemm_body(g_ctx, Wo, C);
}

// ---------------- Flash attention (fp32, causal, 64x64 tiles) ----------------
// grid = (SEQ/64, NH, BATCH); 256 threads (16x16), 4x4 microtile per thread.
#define QS_STRIDE 66   // padded to kill transpose-store bank conflicts
#define SMEM_FLOATS (3 * 64 * QS_STRIDE + 64 * 64)

__global__ void __launch_bounds__(256) flash_fp32() {
    extern __shared__ float sm[];
    float* Qs = sm;                        // [64][66]  Qs[d][i]  (d-major)
    float* Ks = sm + 64 * QS_STRIDE;       // [64][66]  Ks[d][j]
    float* Ps = sm + 2 * 64 * QS_STRIDE;   // [64][66]  Ps[i][j]
    float* Vs = sm + 3 * 64 * QS_STRIDE;   // [64][64]  Vs[j][d]

    const int qt = blockIdx.x;
    const int h  = blockIdx.y;
    const int b  = blockIdx.z;
    const int tid = threadIdx.x;
    const int tx = tid & 15;   // col group (4 cols)
    const int ty = tid >> 4;   // row group (4 rows)

    const float* Qg = g_q + ((size_t)b * SEQ + (size_t)qt * 64) * D_MODEL + h * DK;
    for (int idx = tid; idx < 64 * 64; idx += 256) {
        int i = idx >> 6, d = idx & 63;
        Qs[d * QS_STRIDE + i] = Qg[(size_t)i * D_MODEL + d];
    }

    float m_i[4], l_i[4];
    unsigned long long o2[4][2];
#pragma unroll
    for (int r = 0; r < 4; r++) {
        m_i[r] = -1e30f; l_i[r] = 0.0f;
        o2[r][0] = 0ull; o2[r][1] = 0ull;
    }
    __syncthreads();

    const int qrow0 = qt * 64;

    for (int kt = 0; kt <= qt; kt++) {
        const float* Kg = g_k + ((size_t)b * SEQ + (size_t)kt * 64) * D_MODEL + h * DK;
        const float* Vg = g_v + ((size_t)b * SEQ + (size_t)kt * 64) * D_MODEL + h * DK;
        for (int idx = tid; idx < 64 * 64; idx += 256) {
            int j = idx >> 6, d = idx & 63;
            Ks[d * QS_STRIDE + j] = Kg[(size_t)j * D_MODEL + d];
            Vs[j * 64 + d]        = Vg[(size_t)j * D_MODEL + d];
        }
        __syncthreads();

        // ---- S = Q K^T (4x4 per thread, f32x2 packed over j) ----
        unsigned long long s2[4][2];
#pragma unroll
        for (int r = 0; r < 4; r++) { s2[r][0] = 0ull; s2[r][1] = 0ull; }

#pragma unroll 8
        for (int d = 0; d < 64; d++) {
            const float* qp = &Qs[d * QS_STRIDE + ty * 4];
            const float* kp = &Ks[d * QS_STRIDE + tx * 4];
            unsigned long long kb0 = *(const unsigned long long*)(kp);
            unsigned long long kb1 = *(const unsigned long long*)(kp + 2);
            float a0 = qp[0], a1 = qp[1], a2 = qp[2], a3 = qp[3];
            unsigned long long p0 = f2_pack(a0, a0);
            unsigned long long p1 = f2_pack(a1, a1);
            unsigned long long p2 = f2_pack(a2, a2);
            unsigned long long p3 = f2_pack(a3, a3);
            s2[0][0] = f2_fma(p0, kb0, s2[0][0]); s2[0][1] = f2_fma(p0, kb1, s2[0][1]);
            s2[1][0] = f2_fma(p1, kb0, s2[1][0]); s2[1][1] = f2_fma(p1, kb1, s2[1][1]);
            s2[2][0] = f2_fma(p2, kb0, s2[2][0]); s2[2][1] = f2_fma(p2, kb1, s2[2][1]);
            s2[3][0] = f2_fma(p3, kb0, s2[3][0]); s2[3][1] = f2_fma(p3, kb1, s2[3][1]);
        }

        // ---- masked online softmax per row ----
        const bool diag = (kt == qt);
#pragma unroll
        for (int r = 0; r < 4; r++) {
            float2 u0 = f2_unpack(s2[r][0]);
            float2 u1 = f2_unpack(s2[r][1]);
            float sv[4] = {u0.x, u0.y, u1.x, u1.y};
            const int qi = qrow0 + ty * 4 + r;
#pragma unroll
            for (int c = 0; c < 4; c++) {
                int kj = kt * 64 + tx * 4 + c;
                sv[c] = (!diag || kj <= qi) ? sv[c] * 0.125f : -1e30f;
            }
            float mx = fmaxf(fmaxf(sv[0], sv[1]), fmaxf(sv[2], sv[3]));
#pragma unroll
            for (int off = 1; off < 16; off <<= 1)
                mx = fmaxf(mx, __shfl_xor_sync(0xffffffffu, mx, off));
            float mnew = fmaxf(m_i[r], mx);
            float alpha = __expf(m_i[r] - mnew);
            float ssum = 0.0f;
#pragma unroll
            for (int c = 0; c < 4; c++) {
                sv[c] = __expf(sv[c] - mnew);
                ssum += sv[c];
            }
#pragma unroll
            for (int off = 1; off < 16; off <<= 1)
                ssum += __shfl_xor_sync(0xffffffffu, ssum, off);
            l_i[r] = l_i[r] * alpha + ssum;
            m_i[r] = mnew;
            unsigned long long aa = f2_pack(alpha, alpha);
            o2[r][0] = f2_mul(aa, o2[r][0]);
            o2[r][1] = f2_mul(aa, o2[r][1]);
            float* pp = &Ps[(ty * 4 + r) * QS_STRIDE + tx * 4];
            pp[0] = sv[0]; pp[1] = sv[1]; pp[2] = sv[2]; pp[3] = sv[3];
        }
        __syncthreads();

        // ---- O += P V (thread owns rows ty*4.., d-cols tx*4..) ----
#pragma unroll 4
        for (int j = 0; j < 64; j++) {
            unsigned long long v0 = *(const unsigned long long*)&Vs[j * 64 + tx * 4];
            unsigned long long v1 = *(const unsigned long long*)&Vs[j * 64 + tx * 4 + 2];
#pragma unroll
            for (int r = 0; r < 4; r++) {
                float p = Ps[(ty * 4 + r) * QS_STRIDE + j];
                unsigned long long pp = f2_pack(p, p);
                o2[r][0] = f2_fma(pp, v0, o2[r][0]);
                o2[r][1] = f2_fma(pp, v1, o2[r][1]);
            }
        }
        __syncthreads();
    }

    // ---- normalize + write ctx ([B,S,D] layout) ----
    float* Og = g_ctx + ((size_t)b * SEQ + (size_t)qt * 64) * D_MODEL + h * DK;
#pragma unroll
    for (int r = 0; r < 4; r++) {
        float inv = 1.0f / l_i[r];
        float2 c0 = f2_unpack(o2[r][0]);
        float2 c1 = f2_unpack(o2[r][1]);
        *(float4*)&Og[(size_t)(ty * 4 + r) * D_MODEL + tx * 4] =
            make_float4(c0.x * inv, c0.y * inv, c1.x * inv, c1.y * inv);
    }
}

// ---------------- launch ----------------
extern "C" void kernel_launch(void* const* d_in, const int* in_sizes, int n_in,
                              void* d_out, int out_size) {
    (void)in_sizes; (void)n_in; (void)out_size;
    const float* x  = (const float*)d_in[0];
    const float* Wq = (const float*)d_in[1];
    const float* Wk = (const float*)d_in[2];
    const float* Wv = (const float*)d_in[3];
    const float* Wo = (const float*)d_in[4];
    float* out = (float*)d_out;

    qkv_gemm<<<dim3(8, 32, 3), 256>>>(x, Wq, Wk, Wv);

    const int smem_bytes = SMEM_FLOATS * (int)sizeof(float);
    cudaFuncSetAttribute(flash_fp32, cudaFuncAttributeMaxDynamicSharedMemorySize,
                         smem_bytes);
    flash_fp32<<<dim3(SEQ / 64, NH, BATCH), 256, smem_bytes>>>();

    out_gemm<<<dim3(8, 32, 1), 256>>>(Wo, out);
}

// round 3
// speedup vs baseline: 1.5518x; 1.5518x over previous
#include <cuda_runtime.h>
#include <cuda_bf16.h>
#include <cstdint>
#include <math.h>

#define D_MODEL 1024
#define NH      16
#define DK      64
#define BATCH   2
#define SEQ     2048
#define M_TOT   (BATCH * SEQ)   // 4096
#define MM      (D_MODEL * D_MODEL)

// ---------------- scratch (static device memory; no allocations) ----------------
__device__ float g_q[M_TOT * D_MODEL];
__device__ float g_k[M_TOT * D_MODEL];
__device__ float g_v[M_TOT * D_MODEL];
__device__ float g_ctx[M_TOT * D_MODEL];
__device__ __nv_bfloat16 g_xh[M_TOT * D_MODEL];
__device__ __nv_bfloat16 g_xl[M_TOT * D_MODEL];
__device__ __nv_bfloat16 g_wh[4 * MM];
__device__ __nv_bfloat16 g_wl[4 * MM];
__device__ __nv_bfloat16 g_ch[M_TOT * D_MODEL];
__device__ __nv_bfloat16 g_cl[M_TOT * D_MODEL];

// ================= helpers =================
static __device__ __forceinline__ uint32_t smem_to_u32(const void* p) {
    uint32_t a;
    asm("{ .reg .u64 t; cvta.to.shared.u64 t, %1; cvt.u32.u64 %0, t; }" : "=r"(a) : "l"(p));
    return a;
}
static __device__ __forceinline__ void cp_async16(uint32_t saddr, const void* gaddr) {
    asm volatile("cp.async.cg.shared.global [%0], [%1], 16;" :: "r"(saddr), "l"(gaddr));
}
#define CP_COMMIT() asm volatile("cp.async.commit_group;" ::: "memory")
#define CP_WAIT0()  asm volatile("cp.async.wait_group 0;" ::: "memory")

static __device__ __forceinline__ void ldm_x4(uint32_t* r, uint32_t addr) {
    asm volatile("ldmatrix.sync.aligned.m8n8.x4.shared.b16 {%0,%1,%2,%3}, [%4];"
                 : "=r"(r[0]), "=r"(r[1]), "=r"(r[2]), "=r"(r[3]) : "r"(addr));
}
static __device__ __forceinline__ void mma_bf16(float* d, const uint32_t* a,
                                                uint32_t b0, uint32_t b1) {
    asm volatile(
        "mma.sync.aligned.m16n8k16.row.col.f32.bf16.bf16.f32 "
        "{%0,%1,%2,%3}, {%4,%5,%6,%7}, {%8,%9}, {%0,%1,%2,%3};"
        : "+f"(d[0]), "+f"(d[1]), "+f"(d[2]), "+f"(d[3])
        : "r"(a[0]), "r"(a[1]), "r"(a[2]), "r"(a[3]), "r"(b0), "r"(b1));
}

// ================= split convert: fp32 -> bf16 hi + bf16 lo =================
__global__ void __launch_bounds__(256) cvt_split(const float* __restrict__ in,
                                                 __nv_bfloat16* __restrict__ hi,
                                                 __nv_bfloat16* __restrict__ lo,
                                                 int n) {
    int i = (blockIdx.x * 256 + threadIdx.x) * 4;
    if (i >= n) return;
    float4 v = *(const float4*)(in + i);
    __nv_bfloat16 h0 = __float2bfloat16(v.x);
    __nv_bfloat16 h1 = __float2bfloat16(v.y);
    __nv_bfloat16 h2 = __float2bfloat16(v.z);
    __nv_bfloat16 h3 = __float2bfloat16(v.w);
    __nv_bfloat16 l0 = __float2bfloat16(v.x - __bfloat162float(h0));
    __nv_bfloat16 l1 = __float2bfloat16(v.y - __bfloat162float(h1));
    __nv_bfloat16 l2 = __float2bfloat16(v.z - __bfloat162float(h2));
    __nv_bfloat16 l3 = __float2bfloat16(v.w - __bfloat162float(h3));
    *(__nv_bfloat162*)(hi + i)     = __nv_bfloat162(h0, h1);
    *(__nv_bfloat162*)(hi + i + 2) = __nv_bfloat162(h2, h3);
    *(__nv_bfloat162*)(lo + i)     = __nv_bfloat162(l0, l1);
    *(__nv_bfloat162*)(lo + i + 2) = __nv_bfloat162(l2, l3);
}

// ================= HMMA split-bf16 GEMM =================
// C[.,1024] = A[.,1024] * W[1024,1024]^T, 128x128 CTA tiles, K-chunks of 64.
// smem rows padded to 144 B -> conflict-free ldmatrix/STS.
#define TSTRIDE_B 144                    // bytes per smem row
#define TILE_B    (128 * TSTRIDE_B)      // 18432 B per operand tile
#define STAGE_B   (4 * TILE_B)           // Ah, Al, Bh, Bl
#define GEMM_SMEM (2 * STAGE_B)          // 147456 B
#define NCHUNK    16

__global__ void __launch_bounds__(256, 1)
gemm_tc(const __nv_bfloat16* __restrict__ Ah, const __nv_bfloat16* __restrict__ Al,
        const __nv_bfloat16* __restrict__ Wh0, const __nv_bfloat16* __restrict__ Wl0,
        float* C0, float* C1, float* C2) {
    extern __shared__ char smem[];
    const uint32_t sb = smem_to_u32(smem);
    const int tid  = threadIdx.x;
    const int wid  = tid >> 5;
    const int lane = tid & 31;
    const int z  = blockIdx.z;
    const int m0 = blockIdx.y * 128;
    const int n0 = blockIdx.x * 128;

    const __nv_bfloat16* Bh = Wh0 + (size_t)z * MM;
    const __nv_bfloat16* Bl = Wl0 + (size_t)z * MM;
    float* C = (z == 0) ? C0 : (z == 1) ? C1 : C2;

    // ---- load mapping: thread t -> seg (16B) t&7, rows (t>>3) + 32j ----
    const int seg = tid & 7;
    const int r0  = tid >> 3;   // 0..31

    auto load_chunk = [&](int kc, int s) {
        const uint32_t sbase = sb + s * STAGE_B;
        const int ke = kc * 64 + seg * 8;   // bf16 element offset in K
#pragma unroll
        for (int j = 0; j < 4; j++) {
            const int row = r0 + j * 32;
            const uint32_t soff = row * TSTRIDE_B + seg * 16;
            cp_async16(sbase + 0 * TILE_B + soff, Ah + (size_t)(m0 + row) * D_MODEL + ke);
            cp_async16(sbase + 1 * TILE_B + soff, Al + (size_t)(m0 + row) * D_MODEL + ke);
            cp_async16(sbase + 2 * TILE_B + soff, Bh + (size_t)(n0 + row) * D_MODEL + ke);
            cp_async16(sbase + 3 * TILE_B + soff, Bl + (size_t)(n0 + row) * D_MODEL + ke);
        }
    };

    // ---- warp tiling: 2(M) x 4(N); warp tile 64x32 ----
    const int wm = wid >> 2;    // 0..1
    const int wn = wid & 3;     // 0..3

    // ldmatrix lane addressing (offsets within a stage)
    const uint32_t aRowOff = (uint32_t)((wm * 64 + (lane & 15)) * TSTRIDE_B + (lane >> 4) * 16);
    const int g = lane >> 3;
    const uint32_t bRowOff = (uint32_t)((wn * 32 + (g >> 1) * 8 + (lane & 7)) * TSTRIDE_B + (g & 1) * 16);

    float acc[4][4][4];
#pragma unroll
    for (int i = 0; i < 4; i++)
#pragma unroll
        for (int j = 0; j < 4; j++)
#pragma unroll
            for (int k = 0; k < 4; k++) acc[i][j][k] = 0.0f;

    load_chunk(0, 0);
    CP_COMMIT();

    for (int c = 0; c < NCHUNK; c++) {
        const int s = c & 1;
        CP_WAIT0();
        __syncthreads();
        if (c + 1 < NCHUNK) { load_chunk(c + 1, s ^ 1); CP_COMMIT(); }

        const uint32_t stage = sb + s * STAGE_B;
        const uint32_t ahB = stage + aRowOff;
        const uint32_t alB = ahB + TILE_B;
        const uint32_t bhB = stage + 2 * TILE_B + bRowOff;
        const uint32_t blB = bhB + TILE_B;

#pragma unroll
        for (int kk = 0; kk < 4; kk++) {
            const uint32_t ka = kk * 32;
            uint32_t ah[4][4], al[4][4], bh[2][4], bl[2][4];
#pragma unroll
            for (int mf = 0; mf < 4; mf++) {
                ldm_x4(ah[mf], ahB + mf * (16 * TSTRIDE_B) + ka);
                ldm_x4(al[mf], alB + mf * (16 * TSTRIDE_B) + ka);
            }
#pragma unroll
            for (int p = 0; p < 2; p++) {
                ldm_x4(bh[p], bhB + p * (16 * TSTRIDE_B) + ka);
                ldm_x4(bl[p], blB + p * (16 * TSTRIDE_B) + ka);
            }
#pragma unroll
            for (int mf = 0; mf < 4; mf++) {
#pragma unroll
                for (int nf = 0; nf < 4; nf++) {
                    const int p = nf >> 1, h = (nf & 1) * 2;
                    mma_bf16(acc[mf][nf], ah[mf], bh[p][h], bh[p][h + 1]);
                    mma_bf16(acc[mf][nf], ah[mf], bl[p][h], bl[p][h + 1]);
                    mma_bf16(acc[mf][nf], al[mf], bh[p][h], bh[p][h + 1]);
                }
            }
        }
        __syncthreads();
    }

    // ---- epilogue: fragment -> C ----
    const int rr = lane >> 2;
    const int cc = (lane & 3) * 2;
#pragma unroll
    for (int mf = 0; mf < 4; mf++) {
#pragma unroll
        for (int nf = 0; nf < 4; nf++) {
            float* cp = C + (size_t)(m0 + wm * 64 + mf * 16 + rr) * D_MODEL
                          + n0 + wn * 32 + nf * 8 + cc;
            *(float2*)cp                 = make_float2(acc[mf][nf][0], acc[mf][nf][1]);
            *(float2*)(cp + 8 * D_MODEL) = make_float2(acc[mf][nf][2], acc[mf][nf][3]);
        }
    }
}

// ---------------- packed f32x2 helpers ----------------
static __device__ __forceinline__ unsigned long long f2_pack(float x, float y) {
    unsigned long long r;
    asm("mov.b64 %0, {%1, %2};" : "=l"(r) : "f"(x), "f"(y));
    return r;
}
static __device__ __forceinline__ unsigned long long f2_fma(unsigned long long a,
                                                            unsigned long long b,
                                                            unsigned long long c) {
    unsigned long long r;
    asm("fma.rn.f32x2 %0, %1, %2, %3;" : "=l"(r) : "l"(a), "l"(b), "l"(c));
    return r;
}
static __device__ __forceinline__ unsigned long long f2_mul(unsigned long long a,
                                                            unsigned long long b) {
    unsigned long long r;
    asm("mul.rn.f32x2 %0, %1, %2;" : "=l"(r) : "l"(a), "l"(b));
    return r;
}
static __device__ __forceinline__ float2 f2_unpack(unsigned long long v) {
    float2 f;
    asm("mov.b64 {%0, %1}, %2;" : "=f"(f.x), "=f"(f.y) : "l"(v));
    return f;
}

// ---------------- Flash attention (fp32, causal, 64x64 tiles) ----------------
#define QS_STRIDE 66
#define SMEM_FLOATS (3 * 64 * QS_STRIDE + 64 * 64)

__global__ void __launch_bounds__(256) flash_fp32() {
    extern __shared__ float sm[];
    float* Qs = sm;
    float* Ks = sm + 64 * QS_STRIDE;
    float* Ps = sm + 2 * 64 * QS_STRIDE;
    float* Vs = sm + 3 * 64 * QS_STRIDE;

    const int qt = blockIdx.x;
    const int h  = blockIdx.y;
    const int b  = blockIdx.z;
    const int tid = threadIdx.x;
    const int tx = tid & 15;
    const int ty = tid >> 4;

    const float* Qg = g_q + ((size_t)b * SEQ + (size_t)qt * 64) * D_MODEL + h * DK;
    for (int idx = tid; idx < 64 * 64; idx += 256) {
        int i = idx >> 6, d = idx & 63;
        Qs[d * QS_STRIDE + i] = Qg[(size_t)i * D_MODEL + d];
    }

    float m_i[4], l_i[4];
    unsigned long long o2[4][2];
#pragma unroll
    for (int r = 0; r < 4; r++) {
        m_i[r] = -1e30f; l_i[r] = 0.0f;
        o2[r][0] = 0ull; o2[r][1] = 0ull;
    }
    __syncthreads();

    const int qrow0 = qt * 64;

    for (int kt = 0; kt <= qt; kt++) {
        const float* Kg = g_k + ((size_t)b * SEQ + (size_t)kt * 64) * D_MODEL + h * DK;
        const float* Vg = g_v + ((size_t)b * SEQ + (size_t)kt * 64) * D_MODEL + h * DK;
        for (int idx = tid; idx < 64 * 64; idx += 256) {
            int j = idx >> 6, d = idx & 63;
            Ks[d * QS_STRIDE + j] = Kg[(size_t)j * D_MODEL + d];
            Vs[j * 64 + d]        = Vg[(size_t)j * D_MODEL + d];
        }
        __syncthreads();

        unsigned long long s2[4][2];
#pragma unroll
        for (int r = 0; r < 4; r++) { s2[r][0] = 0ull; s2[r][1] = 0ull; }

#pragma unroll 8
        for (int d = 0; d < 64; d++) {
            const float* qp = &Qs[d * QS_STRIDE + ty * 4];
            const float* kp = &Ks[d * QS_STRIDE + tx * 4];
            unsigned long long kb0 = *(const unsigned long long*)(kp);
            unsigned long long kb1 = *(const unsigned long long*)(kp + 2);
            float a0 = qp[0], a1 = qp[1], a2 = qp[2], a3 = qp[3];
            unsigned long long p0 = f2_pack(a0, a0);
            unsigned long long p1 = f2_pack(a1, a1);
            unsigned long long p2 = f2_pack(a2, a2);
            unsigned long long p3 = f2_pack(a3, a3);
            s2[0][0] = f2_fma(p0, kb0, s2[0][0]); s2[0][1] = f2_fma(p0, kb1, s2[0][1]);
            s2[1][0] = f2_fma(p1, kb0, s2[1][0]); s2[1][1] = f2_fma(p1, kb1, s2[1][1]);
            s2[2][0] = f2_fma(p2, kb0, s2[2][0]); s2[2][1] = f2_fma(p2, kb1, s2[2][1]);
            s2[3][0] = f2_fma(p3, kb0, s2[3][0]); s2[3][1] = f2_fma(p3, kb1, s2[3][1]);
        }

        const bool diag = (kt == qt);
#pragma unroll
        for (int r = 0; r < 4; r++) {
            float2 u0 = f2_unpack(s2[r][0]);
            float2 u1 = f2_unpack(s2[r][1]);
            float sv[4] = {u0.x, u0.y, u1.x, u1.y};
            const int qi = qrow0 + ty * 4 + r;
#pragma unroll
            for (int c = 0; c < 4; c++) {
                int kj = kt * 64 + tx * 4 + c;
                sv[c] = (!diag || kj <= qi) ? sv[c] * 0.125f : -1e30f;
            }
            float mx = fmaxf(fmaxf(sv[0], sv[1]), fmaxf(sv[2], sv[3]));
#pragma unroll
            for (int off = 1; off < 16; off <<= 1)
                mx = fmaxf(mx, __shfl_xor_sync(0xffffffffu, mx, off));
            float mnew = fmaxf(m_i[r], mx);
            float alpha = __expf(m_i[r] - mnew);
            float ssum = 0.0f;
#pragma unroll
            for (int c = 0; c < 4; c++) {
                sv[c] = __expf(sv[c] - mnew);
                ssum += sv[c];
            }
#pragma unroll
            for (int off = 1; off < 16; off <<= 1)
                ssum += __shfl_xor_sync(0xffffffffu, ssum, off);
            l_i[r] = l_i[r] * alpha + ssum;
            m_i[r] = mnew;
            unsigned long long aa = f2_pack(alpha, alpha);
            o2[r][0] = f2_mul(aa, o2[r][0]);
            o2[r][1] = f2_mul(aa, o2[r][1]);
            float* pp = &Ps[(ty * 4 + r) * QS_STRIDE + tx * 4];
            pp[0] = sv[0]; pp[1] = sv[1]; pp[2] = sv[2]; pp[3] = sv[3];
        }
        __syncthreads();

#pragma unroll 4
        for (int j = 0; j < 64; j++) {
            unsigned long long v0 = *(const unsigned long long*)&Vs[j * 64 + tx * 4];
            unsigned long long v1 = *(const unsigned long long*)&Vs[j * 64 + tx * 4 + 2];
#pragma unroll
            for (int r = 0; r < 4; r++) {
                float p = Ps[(ty * 4 + r) * QS_STRIDE + j];
                unsigned long long pp = f2_pack(p, p);
                o2[r][0] = f2_fma(pp, v0, o2[r][0]);
                o2[r][1] = f2_fma(pp, v1, o2[r][1]);
            }
        }
        __syncthreads();
    }

    float* Og = g_ctx + ((size_t)b * SEQ + (size_t)qt * 64) * D_MODEL + h * DK;
#pragma unroll
    for (int r = 0; r < 4; r++) {
        float inv = 1.0f / l_i[r];
        float2 c0 = f2_unpack(o2[r][0]);
        float2 c1 = f2_unpack(o2[r][1]);
        *(float4*)&Og[(size_t)(ty * 4 + r) * D_MODEL + tx * 4] =
            make_float4(c0.x * inv, c0.y * inv, c1.x * inv, c1.y * inv);
    }
}

// ---------------- launch ----------------
extern "C" void kernel_launch(void* const* d_in, const int* in_sizes, int n_in,
                              void* d_out, int out_size) {
    (void)in_sizes; (void)n_in; (void)out_size;
    const float* x  = (const float*)d_in[0];
    const float* Wq = (const float*)d_in[1];
    const float* Wk = (const float*)d_in[2];
    const float* Wv = (const float*)d_in[3];
    const float* Wo = (const float*)d_in[4];
    float* out = (float*)d_out;

    __nv_bfloat16 *xh, *xl, *wh, *wl, *ch, *cl;
    float *q, *k, *v, *ctx;
    cudaGetSymbolAddress((void**)&xh, g_xh);
    cudaGetSymbolAddress((void**)&xl, g_xl);
    cudaGetSymbolAddress((void**)&wh, g_wh);
    cudaGetSymbolAddress((void**)&wl, g_wl);
    cudaGetSymbolAddress((void**)&ch, g_ch);
    cudaGetSymbolAddress((void**)&cl, g_cl);
    cudaGetSymbolAddress((void**)&q, g_q);
    cudaGetSymbolAddress((void**)&k, g_k);
    cudaGetSymbolAddress((void**)&v, g_v);
    cudaGetSymbolAddress((void**)&ctx, g_ctx);

    // split-convert inputs
    cvt_split<<<(M_TOT * D_MODEL / 4 + 255) / 256, 256>>>(x, xh, xl, M_TOT * D_MODEL);
    cvt_split<<<(MM / 4 + 255) / 256, 256>>>(Wq, wh + 0 * MM, wl + 0 * MM, MM);
    cvt_split<<<(MM / 4 + 255) / 256, 256>>>(Wk, wh + 1 * MM, wl + 1 * MM, MM);
    cvt_split<<<(MM / 4 + 255) / 256, 256>>>(Wv, wh + 2 * MM, wl + 2 * MM, MM);
    cvt_split<<<(MM / 4 + 255) / 256, 256>>>(Wo, wh + 3 * MM, wl + 3 * MM, MM);

    cudaFuncSetAttribute(gemm_tc, cudaFuncAttributeMaxDynamicSharedMemorySize, GEMM_SMEM);

    // QKV projection (z selects Wq/Wk/Wv and destination)
    gemm_tc<<<dim3(8, 32, 3), 256, GEMM_SMEM>>>(xh, xl, wh, wl, q, k, v);

    // attention
    const int smem_bytes = SMEM_FLOATS * (int)sizeof(float);
    cudaFuncSetAttribute(flash_fp32, cudaFuncAttributeMaxDynamicSharedMemorySize, smem_bytes);
    flash_fp32<<<dim3(SEQ / 64, NH, BATCH), 256, smem_bytes>>>();

    // output projection
    cvt_split<<<(M_TOT * D_MODEL / 4 + 255) / 256, 256>>>(ctx, ch, cl, M_TOT * D_MODEL);
    gemm_tc<<<dim3(8, 32, 1), 256, GEMM_SMEM>>>(ch, cl, wh + 3 * MM, wl + 3 * MM,
                                                out, out, out);
}

// round 5
// speedup vs baseline: 3.0361x; 1.9565x over previous
#include <cuda_runtime.h>
#include <cuda_bf16.h>
#include <cstdint>
#include <math.h>

#define D_MODEL 1024
#define NH      16
#define DK      64
#define BATCH   2
#define SEQ     2048
#define M_TOT   (BATCH * SEQ)   // 4096
#define MM      (D_MODEL * D_MODEL)

// ---------------- scratch (static device memory; no allocations) ----------------
__device__ __nv_bfloat16 g_xh[M_TOT * D_MODEL];
__device__ __nv_bfloat16 g_xl[M_TOT * D_MODEL];
__device__ __nv_bfloat16 g_wh[4 * MM];
__device__ __nv_bfloat16 g_wl[4 * MM];
__device__ __nv_bfloat16 g_qh[M_TOT * D_MODEL];
__device__ __nv_bfloat16 g_ql[M_TOT * D_MODEL];
__device__ __nv_bfloat16 g_kh[M_TOT * D_MODEL];
__device__ __nv_bfloat16 g_kl[M_TOT * D_MODEL];
__device__ __nv_bfloat16 g_vh[M_TOT * D_MODEL];
__device__ __nv_bfloat16 g_vl[M_TOT * D_MODEL];
__device__ __nv_bfloat16 g_ch[M_TOT * D_MODEL];
__device__ __nv_bfloat16 g_cl[M_TOT * D_MODEL];

// ================= helpers =================
static __device__ __forceinline__ uint32_t smem_to_u32(const void* p) {
    uint32_t a;
    asm("{ .reg .u64 t; cvta.to.shared.u64 t, %1; cvt.u32.u64 %0, t; }" : "=r"(a) : "l"(p));
    return a;
}
static __device__ __forceinline__ void cp_async16(uint32_t saddr, const void* gaddr) {
    asm volatile("cp.async.cg.shared.global [%0], [%1], 16;" :: "r"(saddr), "l"(gaddr));
}
#define CP_COMMIT() asm volatile("cp.async.commit_group;" ::: "memory")
#define CP_WAIT0()  asm volatile("cp.async.wait_group 0;" ::: "memory")

static __device__ __forceinline__ void ldm_x4(uint32_t* r, uint32_t addr) {
    asm volatile("ldmatrix.sync.aligned.m8n8.x4.shared.b16 {%0,%1,%2,%3}, [%4];"
                 : "=r"(r[0]), "=r"(r[1]), "=r"(r[2]), "=r"(r[3]) : "r"(addr));
}
static __device__ __forceinline__ void ldm_x4_trans(uint32_t* r, uint32_t addr) {
    asm volatile("ldmatrix.sync.aligned.m8n8.x4.trans.shared.b16 {%0,%1,%2,%3}, [%4];"
                 : "=r"(r[0]), "=r"(r[1]), "=r"(r[2]), "=r"(r[3]) : "r"(addr));
}
static __device__ __forceinline__ void mma_bf16(float* d, const uint32_t* a,
                                                uint32_t b0, uint32_t b1) {
    asm volatile(
        "mma.sync.aligned.m16n8k16.row.col.f32.bf16.bf16.f32 "
        "{%0,%1,%2,%3}, {%4,%5,%6,%7}, {%8,%9}, {%0,%1,%2,%3};"
        : "+f"(d[0]), "+f"(d[1]), "+f"(d[2]), "+f"(d[3])
        : "r"(a[0]), "r"(a[1]), "r"(a[2]), "r"(a[3]), "r"(b0), "r"(b1));
}
static __device__ __forceinline__ float ex2f(float x) {
    float r;
    asm("ex2.approx.ftz.f32 %0, %1;" : "=f"(r) : "f"(x));
    return r;
}
static __device__ __forceinline__ uint32_t pk_bf2(float x, float y) {
    __nv_bfloat162 t = __floats2bfloat162_rn(x, y);
    return *(uint32_t*)&t;
}

// ================= split convert: fp32 -> bf16 hi + bf16 lo =================
__global__ void __launch_bounds__(256) cvt_split(const float* __restrict__ in,
                                                 __nv_bfloat16* __restrict__ hi,
                                                 __nv_bfloat16* __restrict__ lo,
                                                 int n) {
    int i = (blockIdx.x * 256 + threadIdx.x) * 4;
    if (i >= n) return;
    float4 v = *(const float4*)(in + i);
    __nv_bfloat16 h0 = __float2bfloat16(v.x);
    __nv_bfloat16 h1 = __float2bfloat16(v.y);
    __nv_bfloat16 h2 = __float2bfloat16(v.z);
    __nv_bfloat16 h3 = __float2bfloat16(v.w);
    __nv_bfloat16 l0 = __float2bfloat16(v.x - __bfloat162float(h0));
    __nv_bfloat16 l1 = __float2bfloat16(v.y - __bfloat162float(h1));
    __nv_bfloat16 l2 = __float2bfloat16(v.z - __bfloat162float(h2));
    __nv_bfloat16 l3 = __float2bfloat16(v.w - __bfloat162float(h3));
    *(__nv_bfloat162*)(hi + i)     = __nv_bfloat162(h0, h1);
    *(__nv_bfloat162*)(hi + i + 2) = __nv_bfloat162(h2, h3);
    *(__nv_bfloat162*)(lo + i)     = __nv_bfloat162(l0, l1);
    *(__nv_bfloat162*)(lo + i + 2) = __nv_bfloat162(l2, l3);
}

// ================= HMMA split-bf16 GEMM =================
// C = A[.,1024] * W[1024,1024]^T, 128x128 CTA tiles, K-chunks of 64.
// Epilogue: fp32 (Cf) when Hz==null, else split-bf16 pair (Hz, Lz).
#define TSTRIDE_B 144
#define TILE_B    (128 * TSTRIDE_B)
#define STAGE_B   (4 * TILE_B)
#define GEMM_SMEM (2 * STAGE_B)
#define NCHUNK    16

__global__ void __launch_bounds__(256, 1)
gemm_tc(const __nv_bfloat16* __restrict__ Ah, const __nv_bfloat16* __restrict__ Al,
        const __nv_bfloat16* __restrict__ Wh0, const __nv_bfloat16* __restrict__ Wl0,
        float* Cf,
        __nv_bfloat16* H0, __nv_bfloat16* L0,
        __nv_bfloat16* H1, __nv_bfloat16* L1,
        __nv_bfloat16* H2, __nv_bfloat16* L2) {
    extern __shared__ char smem[];
    const uint32_t sb = smem_to_u32(smem);
    const int tid  = threadIdx.x;
    const int wid  = tid >> 5;
    const int lane = tid & 31;
    const int z  = blockIdx.z;
    const int m0 = blockIdx.y * 128;
    const int n0 = blockIdx.x * 128;

    const __nv_bfloat16* Bh = Wh0 + (size_t)z * MM;
    const __nv_bfloat16* Bl = Wl0 + (size_t)z * MM;
    __nv_bfloat16* Hz = (z == 0) ? H0 : (z == 1) ? H1 : H2;
    __nv_bfloat16* Lz = (z == 0) ? L0 : (z == 1) ? L1 : L2;

    const int seg = tid & 7;
    const int r0  = tid >> 3;

    auto load_chunk = [&](int kc, int s) {
        const uint32_t sbase = sb + s * STAGE_B;
        const int ke = kc * 64 + seg * 8;
#pragma unroll
        for (int j = 0; j < 4; j++) {
            const int row = r0 + j * 32;
            const uint32_t soff = row * TSTRIDE_B + seg * 16;
            cp_async16(sbase + 0 * TILE_B + soff, Ah + (size_t)(m0 + row) * D_MODEL + ke);
            cp_async16(sbase + 1 * TILE_B + soff, Al + (size_t)(m0 + row) * D_MODEL + ke);
            cp_async16(sbase + 2 * TILE_B + soff, Bh + (size_t)(n0 + row) * D_MODEL + ke);
            cp_async16(sbase + 3 * TILE_B + soff, Bl + (size_t)(n0 + row) * D_MODEL + ke);
        }
    };

    const int wm = wid >> 2;
    const int wn = wid & 3;
    const uint32_t aRowOff = (uint32_t)((wm * 64 + (lane & 15)) * TSTRIDE_B + (lane >> 4) * 16);
    const int g = lane >> 3;
    const uint32_t bRowOff = (uint32_t)((wn * 32 + (g >> 1) * 8 + (lane & 7)) * TSTRIDE_B + (g & 1) * 16);

    float acc[4][4][4];
#pragma unroll
    for (int i = 0; i < 4; i++)
#pragma unroll
        for (int j = 0; j < 4; j++)
#pragma unroll
            for (int k = 0; k < 4; k++) acc[i][j][k] = 0.0f;

    load_chunk(0, 0);
    CP_COMMIT();

    for (int c = 0; c < NCHUNK; c++) {
        const int s = c & 1;
        CP_WAIT0();
        __syncthreads();
        if (c + 1 < NCHUNK) { load_chunk(c + 1, s ^ 1); CP_COMMIT(); }

        const uint32_t stage = sb + s * STAGE_B;
        const uint32_t ahB = stage + aRowOff;
        const uint32_t alB = ahB + TILE_B;
        const uint32_t bhB = stage + 2 * TILE_B + bRowOff;
        const uint32_t blB = bhB + TILE_B;

#pragma unroll
        for (int kk = 0; kk < 4; kk++) {
            const uint32_t ka = kk * 32;
            uint32_t ah[4][4], al[4][4], bh[2][4], bl[2][4];
#pragma unroll
            for (int mf = 0; mf < 4; mf++) {
                ldm_x4(ah[mf], ahB + mf * (16 * TSTRIDE_B) + ka);
                ldm_x4(al[mf], alB + mf * (16 * TSTRIDE_B) + ka);
            }
#pragma unroll
            for (int p = 0; p < 2; p++) {
                ldm_x4(bh[p], bhB + p * (16 * TSTRIDE_B) + ka);
                ldm_x4(bl[p], blB + p * (16 * TSTRIDE_B) + ka);
            }
#pragma unroll
            for (int mf = 0; mf < 4; mf++) {
#pragma unroll
                for (int nf = 0; nf < 4; nf++) {
                    const int p = nf >> 1, h = (nf & 1) * 2;
                    mma_bf16(acc[mf][nf], ah[mf], bh[p][h], bh[p][h + 1]);
                    mma_bf16(acc[mf][nf], ah[mf], bl[p][h], bl[p][h + 1]);
                    mma_bf16(acc[mf][nf], al[mf], bh[p][h], bh[p][h + 1]);
                }
            }
        }
        __syncthreads();
    }

    const int rr = lane >> 2;
    const int cc = (lane & 3) * 2;
#pragma unroll
    for (int mf = 0; mf < 4; mf++) {
#pragma unroll
        for (int nf = 0; nf < 4; nf++) {
            const size_t row = (size_t)(m0 + wm * 64 + mf * 16 + rr);
            const int col = n0 + wn * 32 + nf * 8 + cc;
            if (Hz) {
#pragma unroll
                for (int hh = 0; hh < 2; hh++) {
                    float a0 = acc[mf][nf][hh * 2 + 0];
                    float a1 = acc[mf][nf][hh * 2 + 1];
                    __nv_bfloat16 h0 = __float2bfloat16(a0);
                    __nv_bfloat16 h1 = __float2bfloat16(a1);
                    __nv_bfloat16 l0 = __float2bfloat16(a0 - __bfloat162float(h0));
                    __nv_bfloat16 l1 = __float2bfloat16(a1 - __bfloat162float(h1));
                    size_t off = (row + hh * 8) * D_MODEL + col;
                    *(__nv_bfloat162*)(Hz + off) = __nv_bfloat162(h0, h1);
                    *(__nv_bfloat162*)(Lz + off) = __nv_bfloat162(l0, l1);
                }
            } else {
                float* cp = Cf + row * D_MODEL + col;
                *(float2*)cp                 = make_float2(acc[mf][nf][0], acc[mf][nf][1]);
                *(float2*)(cp + 8 * D_MODEL) = make_float2(acc[mf][nf][2], acc[mf][nf][3]);
            }
        }
    }
}

// ================= HMMA flash attention (split-bf16, causal) =================
// CTA: 128 q-rows x one (b,h). 8 warps x 16-row stripes. K-tiles of 64,
// double-buffered cp.async. V consumed row-major via ldmatrix.trans.
#define KSTR 144
#define QTILE_B  (128 * KSTR)           // 18432
#define KVTILE_B (64 * KSTR)            // 9216
#define KVSTAGE_B (4 * KVTILE_B)        // Kh,Kl,Vh,Vl
#define FLASH_SMEM (2 * QTILE_B + 2 * KVSTAGE_B)   // 110592
#define SCL 0.18033688f                 // 0.125 * log2(e)

__global__ void __launch_bounds__(256, 1) flash_tc() {
    extern __shared__ char smf[];
    const uint32_t sb = smem_to_u32(smf);
    const uint32_t sQh = sb;
    const uint32_t sQl = sb + QTILE_B;
    const int tid  = threadIdx.x;
    const int wid  = tid >> 5;
    const int lane = tid & 31;
    const int qt = gridDim.x - 1 - blockIdx.x;    // heavy tiles first
    const int h  = blockIdx.y;
    const int b  = blockIdx.z;
    const int nkt = 2 * qt + 2;
    const size_t tok0 = (size_t)b * SEQ;

    // ---- Q tile load (once) ----
    for (int i = tid; i < 128 * 8; i += 256) {
        const int row = i >> 3, seg = i & 7;
        const size_t goff = (tok0 + qt * 128 + row) * D_MODEL + h * 64 + seg * 8;
        const uint32_t soff = row * KSTR + seg * 16;
        cp_async16(sQh + soff, g_qh + goff);
        cp_async16(sQl + soff, g_ql + goff);
    }
    auto kvbase = [&](int s) { return sb + 2 * QTILE_B + s * KVSTAGE_B; };
    auto loadKV = [&](int kt, int s) {
        const uint32_t base = kvbase(s);
        const int seg = tid & 7, r = tid >> 3;
        const int j0 = kt * 64;
#pragma unroll
        for (int rr2 = 0; rr2 < 2; rr2++) {
            const int row = r + rr2 * 32;
            const size_t goff = (tok0 + j0 + row) * D_MODEL + h * 64 + seg * 8;
            const uint32_t soff = row * KSTR + seg * 16;
            cp_async16(base + 0 * KVTILE_B + soff, g_kh + goff);
            cp_async16(base + 1 * KVTILE_B + soff, g_kl + goff);
            cp_async16(base + 2 * KVTILE_B + soff, g_vh + goff);
            cp_async16(base + 3 * KVTILE_B + soff, g_vl + goff);
        }
    };
    loadKV(0, 0);
    CP_COMMIT();
    CP_WAIT0();
    __syncthreads();

    // ---- Q fragments (held for whole kernel) ----
    uint32_t qhf[4][4], qlf[4][4];
    {
        const uint32_t aoff = (wid * 16 + (lane & 15)) * KSTR + (lane >> 4) * 16;
#pragma unroll
        for (int ka = 0; ka < 4; ka++) {
            ldm_x4(qhf[ka], sQh + aoff + ka * 32);
            ldm_x4(qlf[ka], sQl + aoff + ka * 32);
        }
    }

    float o[8][4];
#pragma unroll
    for (int f = 0; f < 8; f++)
#pragma unroll
        for (int k = 0; k < 4; k++) o[f][k] = 0.0f;
    float m0f = -1e30f, m1f = -1e30f, l0 = 0.0f, l1 = 0.0f;

    const int rmin = qt * 128 + wid * 16;
    const int g8 = lane >> 3;
    const uint32_t boffB = ((g8 >> 1) * 8 + (lane & 7)) * KSTR + (g8 & 1) * 16;
    const uint32_t voffB = (lane & 15) * KSTR + (lane >> 4) * 16;
    const int t2 = lane & 3, gq = lane >> 2;

    for (int kt = 0; kt < nkt; kt++) {
        const int s = kt & 1;
        if (kt + 1 < nkt) { loadKV(kt + 1, s ^ 1); CP_COMMIT(); }
        const uint32_t bK = kvbase(s);
        const int j0 = kt * 64;
        const bool activew = (j0 <= rmin + 15);

        if (activew) {
            float sacc[8][4];
#pragma unroll
            for (int f = 0; f < 8; f++)
#pragma unroll
                for (int k = 0; k < 4; k++) sacc[f][k] = 0.0f;

            // ---- S = Q K^T (3 split terms) ----
#pragma unroll
            for (int ka = 0; ka < 4; ka++) {
#pragma unroll
                for (int nf16 = 0; nf16 < 4; nf16++) {
                    uint32_t kbh[4], kbl[4];
                    const uint32_t ad = bK + nf16 * (16 * KSTR) + boffB + ka * 32;
                    ldm_x4(kbh, ad);
                    ldm_x4(kbl, ad + KVTILE_B);
#pragma unroll
                    for (int h2 = 0; h2 < 2; h2++) {
                        const int f = nf16 * 2 + h2;
                        mma_bf16(sacc[f], qhf[ka], kbh[h2 * 2], kbh[h2 * 2 + 1]);
                        mma_bf16(sacc[f], qhf[ka], kbl[h2 * 2], kbl[h2 * 2 + 1]);
                        mma_bf16(sacc[f], qlf[ka], kbh[h2 * 2], kbh[h2 * 2 + 1]);
                    }
                }
            }

            // ---- causal mask (diagonal tiles only) ----
            const int row0 = rmin + gq, row1 = row0 + 8;
            if (j0 + 63 > rmin) {
#pragma unroll
                for (int f = 0; f < 8; f++) {
                    const int cbase = j0 + f * 8 + t2 * 2;
                    if (cbase     > row0) sacc[f][0] = -1e30f;
                    if (cbase + 1 > row0) sacc[f][1] = -1e30f;
                    if (cbase     > row1) sacc[f][2] = -1e30f;
                    if (cbase + 1 > row1) sacc[f][3] = -1e30f;
                }
            }

            // ---- online softmax (rows g, g+8) ----
            float mx0 = -1e30f, mx1 = -1e30f;
#pragma unroll
            for (int f = 0; f < 8; f++) {
                mx0 = fmaxf(mx0, fmaxf(sacc[f][0], sacc[f][1]));
                mx1 = fmaxf(mx1, fmaxf(sacc[f][2], sacc[f][3]));
            }
#pragma unroll
            for (int off = 1; off < 4; off <<= 1) {
                mx0 = fmaxf(mx0, __shfl_xor_sync(0xffffffffu, mx0, off));
                mx1 = fmaxf(mx1, __shfl_xor_sync(0xffffffffu, mx1, off));
            }
            const float mn0 = fmaxf(m0f, mx0), mn1 = fmaxf(m1f, mx1);
            const float al0 = ex2f((m0f - mn0) * SCL);
            const float al1 = ex2f((m1f - mn1) * SCL);
            m0f = mn0; m1f = mn1;
            float sum0 = 0.0f, sum1 = 0.0f;
#pragma unroll
            for (int f = 0; f < 8; f++) {
                sacc[f][0] = ex2f((sacc[f][0] - mn0) * SCL);
                sacc[f][1] = ex2f((sacc[f][1] - mn0) * SCL);
                sacc[f][2] = ex2f((sacc[f][2] - mn1) * SCL);
                sacc[f][3] = ex2f((sacc[f][3] - mn1) * SCL);
                sum0 += sacc[f][0] + sacc[f][1];
                sum1 += sacc[f][2] + sacc[f][3];
            }
#pragma unroll
            for (int off = 1; off < 4; off <<= 1) {
                sum0 += __shfl_xor_sync(0xffffffffu, sum0, off);
                sum1 += __shfl_xor_sync(0xffffffffu, sum1, off);
            }
            l0 = l0 * al0 + sum0;
            l1 = l1 * al1 + sum1;
#pragma unroll
            for (int f = 0; f < 8; f++) {
                o[f][0] *= al0; o[f][1] *= al0;
                o[f][2] *= al1; o[f][3] *= al1;
            }

            // ---- O += P V (3 split terms; V via ldmatrix.trans) ----
#pragma unroll
            for (int kj = 0; kj < 4; kj++) {
                uint32_t ph[4], pl[4];
                {
                    const float* pa = sacc[2 * kj];
                    const float* pb = sacc[2 * kj + 1];
                    float ra[4], rb[4];
#pragma unroll
                    for (int k = 0; k < 4; k++) {
                        ra[k] = pa[k] - __bfloat162float(__float2bfloat16(pa[k]));
                        rb[k] = pb[k] - __bfloat162float(__float2bfloat16(pb[k]));
                    }
                    ph[0] = pk_bf2(pa[0], pa[1]); ph[1] = pk_bf2(pa[2], pa[3]);
                    ph[2] = pk_bf2(pb[0], pb[1]); ph[3] = pk_bf2(pb[2], pb[3]);
                    pl[0] = pk_bf2(ra[0], ra[1]); pl[1] = pk_bf2(ra[2], ra[3]);
                    pl[2] = pk_bf2(rb[0], rb[1]); pl[3] = pk_bf2(rb[2], rb[3]);
                }
#pragma unroll
                for (int nf16 = 0; nf16 < 4; nf16++) {
                    uint32_t vbh[4], vbl[4];
                    const uint32_t ad = bK + 2 * KVTILE_B + kj * (16 * KSTR) + voffB + nf16 * 32;
                    ldm_x4_trans(vbh, ad);
                    ldm_x4_trans(vbl, ad + KVTILE_B);
#pragma unroll
                    for (int h2 = 0; h2 < 2; h2++) {
                        const int f = nf16 * 2 + h2;
                        mma_bf16(o[f], ph, vbh[h2 * 2], vbh[h2 * 2 + 1]);
                        mma_bf16(o[f], ph, vbl[h2 * 2], vbl[h2 * 2 + 1]);
                        mma_bf16(o[f], pl, vbh[h2 * 2], vbh[h2 * 2 + 1]);
                    }
                }
            }
        }
        if (kt + 1 < nkt) CP_WAIT0();
        __syncthreads();
    }

    // ---- normalize + split-bf16 store of ctx ----
    const float inv0 = 1.0f / l0, inv1 = 1.0f / l1;
    const size_t row0 = tok0 + qt * 128 + wid * 16 + gq;
#pragma unroll
    for (int f = 0; f < 8; f++) {
        const int col = h * 64 + f * 8 + t2 * 2;
        float a0 = o[f][0] * inv0, a1 = o[f][1] * inv0;
        float a2 = o[f][2] * inv1, a3 = o[f][3] * inv1;
        __nv_bfloat16 h0 = __float2bfloat16(a0), h1 = __float2bfloat16(a1);
        __nv_bfloat16 h2 = __float2bfloat16(a2), h3 = __float2bfloat16(a3);
        __nv_bfloat16 e0 = __float2bfloat16(a0 - __bfloat162float(h0));
        __nv_bfloat16 e1 = __float2bfloat16(a1 - __bfloat162float(h1));
        __nv_bfloat16 e2 = __float2bfloat16(a2 - __bfloat162float(h2));
        __nv_bfloat16 e3 = __float2bfloat16(a3 - __bfloat162float(h3));
        *(__nv_bfloat162*)(g_ch + row0 * D_MODEL + col)       = __nv_bfloat162(h0, h1);
        *(__nv_bfloat162*)(g_cl + row0 * D_MODEL + col)       = __nv_bfloat162(e0, e1);
        *(__nv_bfloat162*)(g_ch + (row0 + 8) * D_MODEL + col) = __nv_bfloat162(h2, h3);
        *(__nv_bfloat162*)(g_cl + (row0 + 8) * D_MODEL + col) = __nv_bfloat162(e2, e3);
    }
}

// ---------------- launch ----------------
extern "C" void kernel_launch(void* const* d_in, const int* in_sizes, int n_in,
                              void* d_out, int out_size) {
    (void)in_sizes; (void)n_in; (void)out_size;
    const float* x  = (const float*)d_in[0];
    const float* Wq = (const float*)d_in[1];
    const float* Wk = (const float*)d_in[2];
    const float* Wv = (const float*)d_in[3];
    const float* Wo = (const float*)d_in[4];
    float* out = (float*)d_out;

    __nv_bfloat16 *xh, *xl, *wh, *wl, *qh, *ql, *kh, *kl, *vh, *vl, *ch, *cl;
    cudaGetSymbolAddress((void**)&xh, g_xh);
    cudaGetSymbolAddress((void**)&xl, g_xl);
    cudaGetSymbolAddress((void**)&wh, g_wh);
    cudaGetSymbolAddress((void**)&wl, g_wl);
    cudaGetSymbolAddress((void**)&qh, g_qh);
    cudaGetSymbolAddress((void**)&ql, g_ql);
    cudaGetSymbolAddress((void**)&kh, g_kh);
    cudaGetSymbolAddress((void**)&kl, g_kl);
    cudaGetSymbolAddress((void**)&vh, g_vh);
    cudaGetSymbolAddress((void**)&vl, g_vl);
    cudaGetSymbolAddress((void**)&ch, g_ch);
    cudaGetSymbolAddress((void**)&cl, g_cl);

    cvt_split<<<(M_TOT * D_MODEL / 4 + 255) / 256, 256>>>(x, xh, xl, M_TOT * D_MODEL);
    cvt_split<<<(MM / 4 + 255) / 256, 256>>>(Wq, wh + 0 * MM, wl + 0 * MM, MM);
    cvt_split<<<(MM / 4 + 255) / 256, 256>>>(Wk, wh + 1 * MM, wl + 1 * MM, MM);
    cvt_split<<<(MM / 4 + 255) / 256, 256>>>(Wv, wh + 2 * MM, wl + 2 * MM, MM);
    cvt_split<<<(MM / 4 + 255) / 256, 256>>>(Wo, wh + 3 * MM, wl + 3 * MM, MM);

    cudaFuncSetAttribute(gemm_tc, cudaFuncAttributeMaxDynamicSharedMemorySize, GEMM_SMEM);
    cudaFuncSetAttribute(flash_tc, cudaFuncAttributeMaxDynamicSharedMemorySize, FLASH_SMEM);

    // QKV projection -> split bf16 q/k/v
    gemm_tc<<<dim3(8, 32, 3), 256, GEMM_SMEM>>>(xh, xl, wh, wl, nullptr,
                                                qh, ql, kh, kl, vh, vl);
    // attention -> split bf16 ctx
    flash_tc<<<dim3(SEQ / 128, NH, BATCH), 256, FLASH_SMEM>>>();
    // output projection -> fp32 d_out
    gemm_tc<<<dim3(8, 32, 1), 256, GEMM_SMEM>>>(ch, cl, wh + 3 * MM, wl + 3 * MM, out,
                                                nullptr, nullptr, nullptr, nullptr,
                                                nullptr, nullptr);
}

// round 6
// speedup vs baseline: 3.0468x; 1.0035x over previous
#include <cuda_runtime.h>
#include <cuda_bf16.h>
#include <cstdint>
#include <math.h>

#define D_MODEL 1024
#define NH      16
#define DK      64
#define BATCH   2
#define SEQ     2048
#define M_TOT   (BATCH * SEQ)   // 4096
#define MM      (D_MODEL * D_MODEL)

// ---------------- scratch (static device memory; no allocations) ----------------
__device__ __nv_bfloat16 g_xh[M_TOT * D_MODEL];
__device__ __nv_bfloat16 g_xl[M_TOT * D_MODEL];
__device__ __nv_bfloat16 g_wh[4 * MM];
__device__ __nv_bfloat16 g_wl[4 * MM];
__device__ __nv_bfloat16 g_qh[M_TOT * D_MODEL];
__device__ __nv_bfloat16 g_ql[M_TOT * D_MODEL];
__device__ __nv_bfloat16 g_kh[M_TOT * D_MODEL];
__device__ __nv_bfloat16 g_kl[M_TOT * D_MODEL];
__device__ __nv_bfloat16 g_vh[M_TOT * D_MODEL];
__device__ __nv_bfloat16 g_vl[M_TOT * D_MODEL];
__device__ __nv_bfloat16 g_ch[M_TOT * D_MODEL];
__device__ __nv_bfloat16 g_cl[M_TOT * D_MODEL];

// ================= helpers =================
static __device__ __forceinline__ uint32_t smem_to_u32(const void* p) {
    uint32_t a;
    asm("{ .reg .u64 t; cvta.to.shared.u64 t, %1; cvt.u32.u64 %0, t; }" : "=r"(a) : "l"(p));
    return a;
}
static __device__ __forceinline__ void cp_async16(uint32_t saddr, const void* gaddr) {
    asm volatile("cp.async.cg.shared.global [%0], [%1], 16;" :: "r"(saddr), "l"(gaddr));
}
#define CP_COMMIT() asm volatile("cp.async.commit_group;" ::: "memory")
#define CP_WAIT0()  asm volatile("cp.async.wait_group 0;" ::: "memory")

static __device__ __forceinline__ void ldm_x4(uint32_t* r, uint32_t addr) {
    asm volatile("ldmatrix.sync.aligned.m8n8.x4.shared.b16 {%0,%1,%2,%3}, [%4];"
                 : "=r"(r[0]), "=r"(r[1]), "=r"(r[2]), "=r"(r[3]) : "r"(addr));
}
static __device__ __forceinline__ void ldm_x4_trans(uint32_t* r, uint32_t addr) {
    asm volatile("ldmatrix.sync.aligned.m8n8.x4.trans.shared.b16 {%0,%1,%2,%3}, [%4];"
                 : "=r"(r[0]), "=r"(r[1]), "=r"(r[2]), "=r"(r[3]) : "r"(addr));
}
static __device__ __forceinline__ void mma_bf16(float* d, const uint32_t* a,
                                                uint32_t b0, uint32_t b1) {
    asm volatile(
        "mma.sync.aligned.m16n8k16.row.col.f32.bf16.bf16.f32 "
        "{%0,%1,%2,%3}, {%4,%5,%6,%7}, {%8,%9}, {%0,%1,%2,%3};"
        : "+f"(d[0]), "+f"(d[1]), "+f"(d[2]), "+f"(d[3])
        : "r"(a[0]), "r"(a[1]), "r"(a[2]), "r"(a[3]), "r"(b0), "r"(b1));
}
static __device__ __forceinline__ float ex2f(float x) {
    float r;
    asm("ex2.approx.ftz.f32 %0, %1;" : "=f"(r) : "f"(x));
    return r;
}
static __device__ __forceinline__ uint32_t pk_bf2(float x, float y) {
    __nv_bfloat162 t = __floats2bfloat162_rn(x, y);
    return *(uint32_t*)&t;
}

// ================= fused split convert (one launch for x + 4 weights) =========
__global__ void __launch_bounds__(256) cvt_all(const float* __restrict__ x,
                                               const float* __restrict__ Wq,
                                               const float* __restrict__ Wk,
                                               const float* __restrict__ Wv,
                                               const float* __restrict__ Wo) {
    const int y = blockIdx.y;
    const float* src;
    __nv_bfloat16 *hi, *lo;
    int n;
    if (y < 4) {
        src = (y == 0) ? Wq : (y == 1) ? Wk : (y == 2) ? Wv : Wo;
        hi = g_wh + (size_t)y * MM;
        lo = g_wl + (size_t)y * MM;
        n = MM;
    } else {
        src = x; hi = g_xh; lo = g_xl; n = M_TOT * D_MODEL;
    }
    int i = (blockIdx.x * 256 + threadIdx.x) * 4;
    if (i >= n) return;
    float4 v = *(const float4*)(src + i);
    __nv_bfloat16 h0 = __float2bfloat16(v.x);
    __nv_bfloat16 h1 = __float2bfloat16(v.y);
    __nv_bfloat16 h2 = __float2bfloat16(v.z);
    __nv_bfloat16 h3 = __float2bfloat16(v.w);
    __nv_bfloat16 l0 = __float2bfloat16(v.x - __bfloat162float(h0));
    __nv_bfloat16 l1 = __float2bfloat16(v.y - __bfloat162float(h1));
    __nv_bfloat16 l2 = __float2bfloat16(v.z - __bfloat162float(h2));
    __nv_bfloat16 l3 = __float2bfloat16(v.w - __bfloat162float(h3));
    *(__nv_bfloat162*)(hi + i)     = __nv_bfloat162(h0, h1);
    *(__nv_bfloat162*)(hi + i + 2) = __nv_bfloat162(h2, h3);
    *(__nv_bfloat162*)(lo + i)     = __nv_bfloat162(l0, l1);
    *(__nv_bfloat162*)(lo + i + 2) = __nv_bfloat162(l2, l3);
}

// ================= HMMA split-bf16 GEMM =================
// C = A[.,1024] * W[1024,1024]^T, 128x128 CTA tiles, K-chunks of 64.
// Term-major MMA order + register double-buffered ldmatrix prefetch.
#define TSTRIDE_B 144
#define TILE_B    (128 * TSTRIDE_B)
#define STAGE_B   (4 * TILE_B)
#define GEMM_SMEM (2 * STAGE_B)
#define NCHUNK    16

__global__ void __launch_bounds__(256, 1)
gemm_tc(const __nv_bfloat16* __restrict__ Ah, const __nv_bfloat16* __restrict__ Al,
        const __nv_bfloat16* __restrict__ Wh0, const __nv_bfloat16* __restrict__ Wl0,
        float* Cf,
        __nv_bfloat16* H0, __nv_bfloat16* L0,
        __nv_bfloat16* H1, __nv_bfloat16* L1,
        __nv_bfloat16* H2, __nv_bfloat16* L2) {
    extern __shared__ char smem[];
    const uint32_t sb = smem_to_u32(smem);
    const int tid  = threadIdx.x;
    const int wid  = tid >> 5;
    const int lane = tid & 31;
    const int z  = blockIdx.z;
    const int m0 = blockIdx.y * 128;
    const int n0 = blockIdx.x * 128;

    const __nv_bfloat16* Bh = Wh0 + (size_t)z * MM;
    const __nv_bfloat16* Bl = Wl0 + (size_t)z * MM;
    __nv_bfloat16* Hz = (z == 0) ? H0 : (z == 1) ? H1 : H2;
    __nv_bfloat16* Lz = (z == 0) ? L0 : (z == 1) ? L1 : L2;

    const int seg = tid & 7;
    const int r0  = tid >> 3;

    auto load_chunk = [&](int kc, int s) {
        const uint32_t sbase = sb + s * STAGE_B;
        const int ke = kc * 64 + seg * 8;
#pragma unroll
        for (int j = 0; j < 4; j++) {
            const int row = r0 + j * 32;
            const uint32_t soff = row * TSTRIDE_B + seg * 16;
            cp_async16(sbase + 0 * TILE_B + soff, Ah + (size_t)(m0 + row) * D_MODEL + ke);
            cp_async16(sbase + 1 * TILE_B + soff, Al + (size_t)(m0 + row) * D_MODEL + ke);
            cp_async16(sbase + 2 * TILE_B + soff, Bh + (size_t)(n0 + row) * D_MODEL + ke);
            cp_async16(sbase + 3 * TILE_B + soff, Bl + (size_t)(n0 + row) * D_MODEL + ke);
        }
    };

    const int wm = wid >> 2;
    const int wn = wid & 3;
    const uint32_t aRowOff = (uint32_t)((wm * 64 + (lane & 15)) * TSTRIDE_B + (lane >> 4) * 16);
    const int g = lane >> 3;
    const uint32_t bRowOff = (uint32_t)((wn * 32 + (g >> 1) * 8 + (lane & 7)) * TSTRIDE_B + (g & 1) * 16);

    float acc[4][4][4];
#pragma unroll
    for (int i = 0; i < 4; i++)
#pragma unroll
        for (int j = 0; j < 4; j++)
#pragma unroll
            for (int k = 0; k < 4; k++) acc[i][j][k] = 0.0f;

    load_chunk(0, 0);
    CP_COMMIT();

    for (int c = 0; c < NCHUNK; c++) {
        const int s = c & 1;
        CP_WAIT0();
        __syncthreads();
        if (c + 1 < NCHUNK) { load_chunk(c + 1, s ^ 1); CP_COMMIT(); }

        const uint32_t stage = sb + s * STAGE_B;
        const uint32_t ahB = stage + aRowOff;
        const uint32_t alB = ahB + TILE_B;
        const uint32_t bhB = stage + 2 * TILE_B + bRowOff;
        const uint32_t blB = bhB + TILE_B;

        // register double-buffered fragments
        uint32_t ahf[2][4][4], alf[2][4][4], bhf[2][2][4], blf[2][2][4];

        auto ldfrags = [&](int kk, int pb) {
            const uint32_t ka = kk * 32;
#pragma unroll
            for (int mf = 0; mf < 4; mf++) {
                ldm_x4(ahf[pb][mf], ahB + mf * (16 * TSTRIDE_B) + ka);
                ldm_x4(alf[pb][mf], alB + mf * (16 * TSTRIDE_B) + ka);
            }
#pragma unroll
            for (int p = 0; p < 2; p++) {
                ldm_x4(bhf[pb][p], bhB + p * (16 * TSTRIDE_B) + ka);
                ldm_x4(blf[pb][p], blB + p * (16 * TSTRIDE_B) + ka);
            }
        };

        ldfrags(0, 0);
#pragma unroll
        for (int kk = 0; kk < 4; kk++) {
            const int pb = kk & 1;
            if (kk < 3) ldfrags(kk + 1, pb ^ 1);
            // term-major: all HH, then HL, then LH (reuse distance 16)
#pragma unroll
            for (int mf = 0; mf < 4; mf++)
#pragma unroll
                for (int nf = 0; nf < 4; nf++) {
                    const int p = nf >> 1, h = (nf & 1) * 2;
                    mma_bf16(acc[mf][nf], ahf[pb][mf], bhf[pb][p][h], bhf[pb][p][h + 1]);
                }
#pragma unroll
            for (int mf = 0; mf < 4; mf++)
#pragma unroll
                for (int nf = 0; nf < 4; nf++) {
                    const int p = nf >> 1, h = (nf & 1) * 2;
                    mma_bf16(acc[mf][nf], ahf[pb][mf], blf[pb][p][h], blf[pb][p][h + 1]);
                }
#pragma unroll
            for (int mf = 0; mf < 4; mf++)
#pragma unroll
                for (int nf = 0; nf < 4; nf++) {
                    const int p = nf >> 1, h = (nf & 1) * 2;
                    mma_bf16(acc[mf][nf], alf[pb][mf], bhf[pb][p][h], bhf[pb][p][h + 1]);
                }
        }
        __syncthreads();
    }

    const int rr = lane >> 2;
    const int cc = (lane & 3) * 2;
#pragma unroll
    for (int mf = 0; mf < 4; mf++) {
#pragma unroll
        for (int nf = 0; nf < 4; nf++) {
            const size_t row = (size_t)(m0 + wm * 64 + mf * 16 + rr);
            const int col = n0 + wn * 32 + nf * 8 + cc;
            if (Hz) {
#pragma unroll
                for (int hh = 0; hh < 2; hh++) {
                    float a0 = acc[mf][nf][hh * 2 + 0];
                    float a1 = acc[mf][nf][hh * 2 + 1];
                    __nv_bfloat16 h0 = __float2bfloat16(a0);
                    __nv_bfloat16 h1 = __float2bfloat16(a1);
                    __nv_bfloat16 l0 = __float2bfloat16(a0 - __bfloat162float(h0));
                    __nv_bfloat16 l1 = __float2bfloat16(a1 - __bfloat162float(h1));
                    size_t off = (row + hh * 8) * D_MODEL + col;
                    *(__nv_bfloat162*)(Hz + off) = __nv_bfloat162(h0, h1);
                    *(__nv_bfloat162*)(Lz + off) = __nv_bfloat162(l0, l1);
                }
            } else {
                float* cp = Cf + row * D_MODEL + col;
                *(float2*)cp                 = make_float2(acc[mf][nf][0], acc[mf][nf][1]);
                *(float2*)(cp + 8 * D_MODEL) = make_float2(acc[mf][nf][2], acc[mf][nf][3]);
            }
        }
    }
}

// ================= HMMA flash attention (split-bf16, causal) =================
#define KSTR 144
#define QTILE_B  (128 * KSTR)
#define KVTILE_B (64 * KSTR)
#define KVSTAGE_B (4 * KVTILE_B)
#define FLASH_SMEM (2 * QTILE_B + 2 * KVSTAGE_B)   // 110592
#define SCL 0.18033688f                 // 0.125 * log2(e)

__global__ void __launch_bounds__(256, 1) flash_tc() {
    extern __shared__ char smf[];
    const uint32_t sb = smem_to_u32(smf);
    const uint32_t sQh = sb;
    const uint32_t sQl = sb + QTILE_B;
    const int tid  = threadIdx.x;
    const int wid  = tid >> 5;
    const int lane = tid & 31;
    const int qt = gridDim.x - 1 - blockIdx.x;    // heavy tiles first
    const int h  = blockIdx.y;
    const int b  = blockIdx.z;
    const int nkt = 2 * qt + 2;
    const size_t tok0 = (size_t)b * SEQ;

    for (int i = tid; i < 128 * 8; i += 256) {
        const int row = i >> 3, seg = i & 7;
        const size_t goff = (tok0 + qt * 128 + row) * D_MODEL + h * 64 + seg * 8;
        const uint32_t soff = row * KSTR + seg * 16;
        cp_async16(sQh + soff, g_qh + goff);
        cp_async16(sQl + soff, g_ql + goff);
    }
    auto kvbase = [&](int s) { return sb + 2 * QTILE_B + s * KVSTAGE_B; };
    auto loadKV = [&](int kt, int s) {
        const uint32_t base = kvbase(s);
        const int seg = tid & 7, r = tid >> 3;
        const int j0 = kt * 64;
#pragma unroll
        for (int rr2 = 0; rr2 < 2; rr2++) {
            const int row = r + rr2 * 32;
            const size_t goff = (tok0 + j0 + row) * D_MODEL + h * 64 + seg * 8;
            const uint32_t soff = row * KSTR + seg * 16;
            cp_async16(base + 0 * KVTILE_B + soff, g_kh + goff);
            cp_async16(base + 1 * KVTILE_B + soff, g_kl + goff);
            cp_async16(base + 2 * KVTILE_B + soff, g_vh + goff);
            cp_async16(base + 3 * KVTILE_B + soff, g_vl + goff);
        }
    };
    loadKV(0, 0);
    CP_COMMIT();
    CP_WAIT0();
    __syncthreads();

    uint32_t qhf[4][4], qlf[4][4];
    {
        const uint32_t aoff = (wid * 16 + (lane & 15)) * KSTR + (lane >> 4) * 16;
#pragma unroll
        for (int ka = 0; ka < 4; ka++) {
            ldm_x4(qhf[ka], sQh + aoff + ka * 32);
            ldm_x4(qlf[ka], sQl + aoff + ka * 32);
        }
    }

    float o[8][4];
#pragma unroll
    for (int f = 0; f < 8; f++)
#pragma unroll
        for (int k = 0; k < 4; k++) o[f][k] = 0.0f;
    float m0f = -1e30f, m1f = -1e30f, l0 = 0.0f, l1 = 0.0f;

    const int rmin = qt * 128 + wid * 16;
    const int g8 = lane >> 3;
    const uint32_t boffB = ((g8 >> 1) * 8 + (lane & 7)) * KSTR + (g8 & 1) * 16;
    const uint32_t voffB = (lane & 15) * KSTR + (lane >> 4) * 16;
    const int t2 = lane & 3, gq = lane >> 2;

    for (int kt = 0; kt < nkt; kt++) {
        const int s = kt & 1;
        if (kt + 1 < nkt) { loadKV(kt + 1, s ^ 1); CP_COMMIT(); }
        const uint32_t bK = kvbase(s);
        const int j0 = kt * 64;
        const bool activew = (j0 <= rmin + 15);

        if (activew) {
            float sacc[8][4];
#pragma unroll
            for (int f = 0; f < 8; f++)
#pragma unroll
                for (int k = 0; k < 4; k++) sacc[f][k] = 0.0f;

            // ---- S = Q K^T, term-major per ka ----
#pragma unroll
            for (int ka = 0; ka < 4; ka++) {
                uint32_t kbh[4][4], kbl[4][4];
#pragma unroll
                for (int nf16 = 0; nf16 < 4; nf16++) {
                    const uint32_t ad = bK + nf16 * (16 * KSTR) + boffB + ka * 32;
                    ldm_x4(kbh[nf16], ad);
                    ldm_x4(kbl[nf16], ad + KVTILE_B);
                }
#pragma unroll
                for (int nf16 = 0; nf16 < 4; nf16++)
#pragma unroll
                    for (int h2 = 0; h2 < 2; h2++)
                        mma_bf16(sacc[nf16 * 2 + h2], qhf[ka],
                                 kbh[nf16][h2 * 2], kbh[nf16][h2 * 2 + 1]);
#pragma unroll
                for (int nf16 = 0; nf16 < 4; nf16++)
#pragma unroll
                    for (int h2 = 0; h2 < 2; h2++)
                        mma_bf16(sacc[nf16 * 2 + h2], qhf[ka],
                                 kbl[nf16][h2 * 2], kbl[nf16][h2 * 2 + 1]);
#pragma unroll
                for (int nf16 = 0; nf16 < 4; nf16++)
#pragma unroll
                    for (int h2 = 0; h2 < 2; h2++)
                        mma_bf16(sacc[nf16 * 2 + h2], qlf[ka],
                                 kbh[nf16][h2 * 2], kbh[nf16][h2 * 2 + 1]);
            }

            // ---- causal mask (diagonal tiles only) ----
            const int row0 = rmin + gq, row1 = row0 + 8;
            if (j0 + 63 > rmin) {
#pragma unroll
                for (int f = 0; f < 8; f++) {
                    const int cbase = j0 + f * 8 + t2 * 2;
                    if (cbase     > row0) sacc[f][0] = -1e30f;
                    if (cbase + 1 > row0) sacc[f][1] = -1e30f;
                    if (cbase     > row1) sacc[f][2] = -1e30f;
                    if (cbase + 1 > row1) sacc[f][3] = -1e30f;
                }
            }

            // ---- online softmax (rows gq, gq+8) ----
            float mx0 = -1e30f, mx1 = -1e30f;
#pragma unroll
            for (int f = 0; f < 8; f++) {
                mx0 = fmaxf(mx0, fmaxf(sacc[f][0], sacc[f][1]));
                mx1 = fmaxf(mx1, fmaxf(sacc[f][2], sacc[f][3]));
            }
#pragma unroll
            for (int off = 1; off < 4; off <<= 1) {
                mx0 = fmaxf(mx0, __shfl_xor_sync(0xffffffffu, mx0, off));
                mx1 = fmaxf(mx1, __shfl_xor_sync(0xffffffffu, mx1, off));
            }
            const float mn0 = fmaxf(m0f, mx0), mn1 = fmaxf(m1f, mx1);
            const float al0 = ex2f((m0f - mn0) * SCL);
            const float al1 = ex2f((m1f - mn1) * SCL);
            m0f = mn0; m1f = mn1;
            float sum0 = 0.0f, sum1 = 0.0f;
#pragma unroll
            for (int f = 0; f < 8; f++) {
                sacc[f][0] = ex2f((sacc[f][0] - mn0) * SCL);
                sacc[f][1] = ex2f((sacc[f][1] - mn0) * SCL);
                sacc[f][2] = ex2f((sacc[f][2] - mn1) * SCL);
                sacc[f][3] = ex2f((sacc[f][3] - mn1) * SCL);
                sum0 += sacc[f][0] + sacc[f][1];
                sum1 += sacc[f][2] + sacc[f][3];
            }
#pragma unroll
            for (int off = 1; off < 4; off <<= 1) {
                sum0 += __shfl_xor_sync(0xffffffffu, sum0, off);
                sum1 += __shfl_xor_sync(0xffffffffu, sum1, off);
            }
            l0 = l0 * al0 + sum0;
            l1 = l1 * al1 + sum1;
#pragma unroll
            for (int f = 0; f < 8; f++) {
                o[f][0] *= al0; o[f][1] *= al0;
                o[f][2] *= al1; o[f][3] *= al1;
            }

            // ---- O += P V, term-major per kj ----
#pragma unroll
            for (int kj = 0; kj < 4; kj++) {
                uint32_t ph[4], pl[4];
                {
                    const float* pa = sacc[2 * kj];
                    const float* pb = sacc[2 * kj + 1];
                    float ra[4], rb[4];
#pragma unroll
                    for (int k = 0; k < 4; k++) {
                        ra[k] = pa[k] - __bfloat162float(__float2bfloat16(pa[k]));
                        rb[k] = pb[k] - __bfloat162float(__float2bfloat16(pb[k]));
                    }
                    ph[0] = pk_bf2(pa[0], pa[1]); ph[1] = pk_bf2(pa[2], pa[3]);
                    ph[2] = pk_bf2(pb[0], pb[1]); ph[3] = pk_bf2(pb[2], pb[3]);
                    pl[0] = pk_bf2(ra[0], ra[1]); pl[1] = pk_bf2(ra[2], ra[3]);
                    pl[2] = pk_bf2(rb[0], rb[1]); pl[3] = pk_bf2(rb[2], rb[3]);
                }
                uint32_t vbh[4][4], vbl[4][4];
#pragma unroll
                for (int nf16 = 0; nf16 < 4; nf16++) {
                    const uint32_t ad = bK + 2 * KVTILE_B + kj * (16 * KSTR) + voffB + nf16 * 32;
                    ldm_x4_trans(vbh[nf16], ad);
                    ldm_x4_trans(vbl[nf16], ad + KVTILE_B);
                }
#pragma unroll
                for (int nf16 = 0; nf16 < 4; nf16++)
#pragma unroll
                    for (int h2 = 0; h2 < 2; h2++)
                        mma_bf16(o[nf16 * 2 + h2], ph,
                                 vbh[nf16][h2 * 2], vbh[nf16][h2 * 2 + 1]);
#pragma unroll
                for (int nf16 = 0; nf16 < 4; nf16++)
#pragma unroll
                    for (int h2 = 0; h2 < 2; h2++)
                        mma_bf16(o[nf16 * 2 + h2], ph,
                                 vbl[nf16][h2 * 2], vbl[nf16][h2 * 2 + 1]);
#pragma unroll
                for (int nf16 = 0; nf16 < 4; nf16++)
#pragma unroll
                    for (int h2 = 0; h2 < 2; h2++)
                        mma_bf16(o[nf16 * 2 + h2], pl,
                                 vbh[nf16][h2 * 2], vbh[nf16][h2 * 2 + 1]);
            }
        }
        if (kt + 1 < nkt) CP_WAIT0();
        __syncthreads();
    }

    // ---- normalize + split-bf16 store of ctx ----
    const float inv0 = 1.0f / l0, inv1 = 1.0f / l1;
    const size_t row0 = tok0 + qt * 128 + wid * 16 + gq;
#pragma unroll
    for (int f = 0; f < 8; f++) {
        const int col = h * 64 + f * 8 + t2 * 2;
        float a0 = o[f][0] * inv0, a1 = o[f][1] * inv0;
        float a2 = o[f][2] * inv1, a3 = o[f][3] * inv1;
        __nv_bfloat16 h0 = __float2bfloat16(a0), h1 = __float2bfloat16(a1);
        __nv_bfloat16 h2 = __float2bfloat16(a2), h3 = __float2bfloat16(a3);
        __nv_bfloat16 e0 = __float2bfloat16(a0 - __bfloat162float(h0));
        __nv_bfloat16 e1 = __float2bfloat16(a1 - __bfloat162float(h1));
        __nv_bfloat16 e2 = __float2bfloat16(a2 - __bfloat162float(h2));
        __nv_bfloat16 e3 = __float2bfloat16(a3 - __bfloat162float(h3));
        *(__nv_bfloat162*)(g_ch + row0 * D_MODEL + col)       = __nv_bfloat162(h0, h1);
        *(__nv_bfloat162*)(g_cl + row0 * D_MODEL + col)       = __nv_bfloat162(e0, e1);
        *(__nv_bfloat162*)(g_ch + (row0 + 8) * D_MODEL + col) = __nv_bfloat162(h2, h3);
        *(__nv_bfloat162*)(g_cl + (row0 + 8) * D_MODEL + col) = __nv_bfloat162(e2, e3);
    }
}

// ---------------- launch ----------------
extern "C" void kernel_launch(void* const* d_in, const int* in_sizes, int n_in,
                              void* d_out, int out_size) {
    (void)in_sizes; (void)n_in; (void)out_size;
    const float* x  = (const float*)d_in[0];
    const float* Wq = (const float*)d_in[1];
    const float* Wk = (const float*)d_in[2];
    const float* Wv = (const float*)d_in[3];
    const float* Wo = (const float*)d_in[4];
    float* out = (float*)d_out;

    __nv_bfloat16 *xh, *xl, *wh, *wl, *qh, *ql, *kh, *kl, *vh, *vl, *ch, *cl;
    cudaGetSymbolAddress((void**)&xh, g_xh);
    cudaGetSymbolAddress((void**)&xl, g_xl);
    cudaGetSymbolAddress((void**)&wh, g_wh);
    cudaGetSymbolAddress((void**)&wl, g_wl);
    cudaGetSymbolAddress((void**)&qh, g_qh);
    cudaGetSymbolAddress((void**)&ql, g_ql);
    cudaGetSymbolAddress((void**)&kh, g_kh);
    cudaGetSymbolAddress((void**)&kl, g_kl);
    cudaGetSymbolAddress((void**)&vh, g_vh);
    cudaGetSymbolAddress((void**)&vl, g_vl);
    cudaGetSymbolAddress((void**)&ch, g_ch);
    cudaGetSymbolAddress((void**)&cl, g_cl);

    // one fused convert launch: y=0..3 weights, y=4 x
    cvt_all<<<dim3(M_TOT * D_MODEL / 4 / 256, 5), 256>>>(x, Wq, Wk, Wv, Wo);

    cudaFuncSetAttribute(gemm_tc, cudaFuncAttributeMaxDynamicSharedMemorySize, GEMM_SMEM);
    cudaFuncSetAttribute(flash_tc, cudaFuncAttributeMaxDynamicSharedMemorySize, FLASH_SMEM);

    gemm_tc<<<dim3(8, 32, 3), 256, GEMM_SMEM>>>(xh, xl, wh, wl, nullptr,
                                                qh, ql, kh, kl, vh, vl);
    flash_tc<<<dim3(SEQ / 128, NH, BATCH), 256, FLASH_SMEM>>>();
    gemm_tc<<<dim3(8, 32, 1), 256, GEMM_SMEM>>>(ch, cl, wh + 3 * MM, wl + 3 * MM, out,
                                                nullptr, nullptr, nullptr, nullptr,
                                                nullptr, nullptr);
}

// round 7
// speedup vs baseline: 3.0571x; 1.0034x over previous
#include <cuda_runtime.h>
#include <cuda_bf16.h>
#include <cstdint>
#include <math.h>

#define D_MODEL 1024
#define NH      16
#define DK      64
#define BATCH   2
#define SEQ     2048
#define M_TOT   (BATCH * SEQ)   // 4096
#define MM      (D_MODEL * D_MODEL)

// ---------------- scratch (static device memory; no allocations) ----------------
__device__ __nv_bfloat16 g_xh[M_TOT * D_MODEL];
__device__ __nv_bfloat16 g_xl[M_TOT * D_MODEL];
__device__ __nv_bfloat16 g_wh[4 * MM];
__device__ __nv_bfloat16 g_wl[4 * MM];
__device__ __nv_bfloat16 g_qh[M_TOT * D_MODEL];
__device__ __nv_bfloat16 g_ql[M_TOT * D_MODEL];
__device__ __nv_bfloat16 g_kh[M_TOT * D_MODEL];
__device__ __nv_bfloat16 g_kl[M_TOT * D_MODEL];
__device__ __nv_bfloat16 g_vh[M_TOT * D_MODEL];
__device__ __nv_bfloat16 g_vl[M_TOT * D_MODEL];
__device__ __nv_bfloat16 g_ch[M_TOT * D_MODEL];
__device__ __nv_bfloat16 g_cl[M_TOT * D_MODEL];

// ================= helpers =================
static __device__ __forceinline__ uint32_t smem_to_u32(const void* p) {
    uint32_t a;
    asm("{ .reg .u64 t; cvta.to.shared.u64 t, %1; cvt.u32.u64 %0, t; }" : "=r"(a) : "l"(p));
    return a;
}
static __device__ __forceinline__ void cp_async16(uint32_t saddr, const void* gaddr) {
    asm volatile("cp.async.cg.shared.global [%0], [%1], 16;" :: "r"(saddr), "l"(gaddr));
}
#define CP_COMMIT() asm volatile("cp.async.commit_group;" ::: "memory")
#define CP_WAIT0()  asm volatile("cp.async.wait_group 0;" ::: "memory")

static __device__ __forceinline__ void ldm_x4(uint32_t* r, uint32_t addr) {
    asm volatile("ldmatrix.sync.aligned.m8n8.x4.shared.b16 {%0,%1,%2,%3}, [%4];"
                 : "=r"(r[0]), "=r"(r[1]), "=r"(r[2]), "=r"(r[3]) : "r"(addr));
}
static __device__ __forceinline__ void ldm_x4_trans(uint32_t* r, uint32_t addr) {
    asm volatile("ldmatrix.sync.aligned.m8n8.x4.trans.shared.b16 {%0,%1,%2,%3}, [%4];"
                 : "=r"(r[0]), "=r"(r[1]), "=r"(r[2]), "=r"(r[3]) : "r"(addr));
}
static __device__ __forceinline__ void mma_bf16(float* d, const uint32_t* a,
                                                uint32_t b0, uint32_t b1) {
    asm volatile(
        "mma.sync.aligned.m16n8k16.row.col.f32.bf16.bf16.f32 "
        "{%0,%1,%2,%3}, {%4,%5,%6,%7}, {%8,%9}, {%0,%1,%2,%3};"
        : "+f"(d[0]), "+f"(d[1]), "+f"(d[2]), "+f"(d[3])
        : "r"(a[0]), "r"(a[1]), "r"(a[2]), "r"(a[3]), "r"(b0), "r"(b1));
}
static __device__ __forceinline__ float ex2f(float x) {
    float r;
    asm("ex2.approx.ftz.f32 %0, %1;" : "=f"(r) : "f"(x));
    return r;
}
static __device__ __forceinline__ uint32_t pk_bf2(float x, float y) {
    __nv_bfloat162 t = __floats2bfloat162_rn(x, y);
    return *(uint32_t*)&t;
}

// ================= fused split convert (one launch for x + 4 weights) =========
__global__ void __launch_bounds__(256) cvt_all(const float* __restrict__ x,
                                               const float* __restrict__ Wq,
                                               const float* __restrict__ Wk,
                                               const float* __restrict__ Wv,
                                               const float* __restrict__ Wo) {
    const int y = blockIdx.y;
    const float* src;
    __nv_bfloat16 *hi, *lo;
    int n;
    if (y < 4) {
        src = (y == 0) ? Wq : (y == 1) ? Wk : (y == 2) ? Wv : Wo;
        hi = g_wh + (size_t)y * MM;
        lo = g_wl + (size_t)y * MM;
        n = MM;
    } else {
        src = x; hi = g_xh; lo = g_xl; n = M_TOT * D_MODEL;
    }
    int i = (blockIdx.x * 256 + threadIdx.x) * 4;
    if (i >= n) return;
    float4 v = *(const float4*)(src + i);
    __nv_bfloat16 h0 = __float2bfloat16(v.x);
    __nv_bfloat16 h1 = __float2bfloat16(v.y);
    __nv_bfloat16 h2 = __float2bfloat16(v.z);
    __nv_bfloat16 h3 = __float2bfloat16(v.w);
    __nv_bfloat16 l0 = __float2bfloat16(v.x - __bfloat162float(h0));
    __nv_bfloat16 l1 = __float2bfloat16(v.y - __bfloat162float(h1));
    __nv_bfloat16 l2 = __float2bfloat16(v.z - __bfloat162float(h2));
    __nv_bfloat16 l3 = __float2bfloat16(v.w - __bfloat162float(h3));
    *(__nv_bfloat162*)(hi + i)     = __nv_bfloat162(h0, h1);
    *(__nv_bfloat162*)(hi + i + 2) = __nv_bfloat162(h2, h3);
    *(__nv_bfloat162*)(lo + i)     = __nv_bfloat162(l0, l1);
    *(__nv_bfloat162*)(lo + i + 2) = __nv_bfloat162(l2, l3);
}

// ================= HMMA split-bf16 GEMM (2 CTAs/SM) =================
// C = A[.,1024] * W[1024,1024]^T, 128x128 CTA tiles, K-chunks of 32.
// Rows at 80B stride: {r*80 mod 128} covers all 8 16B banks -> conflict-free
// ldmatrix and optimal STS. smem 80KB/CTA -> 2 CTAs resident.
#define TSTRIDE_B 80
#define TILE_B    (128 * TSTRIDE_B)      // 10240
#define STAGE_B   (4 * TILE_B)           // 40960: Ah, Al, Bh, Bl
#define GEMM_SMEM (2 * STAGE_B)          // 81920
#define NCHUNK    32

__global__ void __launch_bounds__(256, 2)
gemm_tc(const __nv_bfloat16* __restrict__ Ah, const __nv_bfloat16* __restrict__ Al,
        const __nv_bfloat16* __restrict__ Wh0, const __nv_bfloat16* __restrict__ Wl0,
        float* Cf,
        __nv_bfloat16* H0, __nv_bfloat16* L0,
        __nv_bfloat16* H1, __nv_bfloat16* L1,
        __nv_bfloat16* H2, __nv_bfloat16* L2) {
    extern __shared__ char smem[];
    const uint32_t sb = smem_to_u32(smem);
    const int tid  = threadIdx.x;
    const int wid  = tid >> 5;
    const int lane = tid & 31;
    const int z  = blockIdx.z;
    const int m0 = blockIdx.y * 128;
    const int n0 = blockIdx.x * 128;

    const __nv_bfloat16* Bh = Wh0 + (size_t)z * MM;
    const __nv_bfloat16* Bl = Wl0 + (size_t)z * MM;
    __nv_bfloat16* Hz = (z == 0) ? H0 : (z == 1) ? H1 : H2;
    __nv_bfloat16* Lz = (z == 0) ? L0 : (z == 1) ? L1 : L2;

    // load mapping: thread -> seg (16B within 64B row) tid&3, rows tid>>2 and +64
    const int seg = tid & 3;
    const int r0  = tid >> 2;   // 0..63

    auto load_chunk = [&](int kc, int s) {
        const uint32_t sbase = sb + s * STAGE_B;
        const int ke = kc * 32 + seg * 8;   // bf16 element offset in K
#pragma unroll
        for (int j = 0; j < 2; j++) {
            const int row = r0 + j * 64;
            const uint32_t soff = row * TSTRIDE_B + seg * 16;
            cp_async16(sbase + 0 * TILE_B + soff, Ah + (size_t)(m0 + row) * D_MODEL + ke);
            cp_async16(sbase + 1 * TILE_B + soff, Al + (size_t)(m0 + row) * D_MODEL + ke);
            cp_async16(sbase + 2 * TILE_B + soff, Bh + (size_t)(n0 + row) * D_MODEL + ke);
            cp_async16(sbase + 3 * TILE_B + soff, Bl + (size_t)(n0 + row) * D_MODEL + ke);
        }
    };

    const int wm = wid >> 2;
    const int wn = wid & 3;
    const uint32_t aRowOff = (uint32_t)((wm * 64 + (lane & 15)) * TSTRIDE_B + (lane >> 4) * 16);
    const int g = lane >> 3;
    const uint32_t bRowOff = (uint32_t)((wn * 32 + (g >> 1) * 8 + (lane & 7)) * TSTRIDE_B + (g & 1) * 16);

    float acc[4][4][4];
#pragma unroll
    for (int i = 0; i < 4; i++)
#pragma unroll
        for (int j = 0; j < 4; j++)
#pragma unroll
            for (int k = 0; k < 4; k++) acc[i][j][k] = 0.0f;

    load_chunk(0, 0);
    CP_COMMIT();

    for (int c = 0; c < NCHUNK; c++) {
        const int s = c & 1;
        CP_WAIT0();
        __syncthreads();
        if (c + 1 < NCHUNK) { load_chunk(c + 1, s ^ 1); CP_COMMIT(); }

        const uint32_t stage = sb + s * STAGE_B;
        const uint32_t ahB = stage + aRowOff;
        const uint32_t alB = ahB + TILE_B;
        const uint32_t bhB = stage + 2 * TILE_B + bRowOff;
        const uint32_t blB = bhB + TILE_B;

#pragma unroll
        for (int kk = 0; kk < 2; kk++) {
            const uint32_t ka = kk * 32;
            uint32_t ahf[4][4], alf[4][4], bhf[2][4], blf[2][4];
#pragma unroll
            for (int mf = 0; mf < 4; mf++) {
                ldm_x4(ahf[mf], ahB + mf * (16 * TSTRIDE_B) + ka);
                ldm_x4(alf[mf], alB + mf * (16 * TSTRIDE_B) + ka);
            }
#pragma unroll
            for (int p = 0; p < 2; p++) {
                ldm_x4(bhf[p], bhB + p * (16 * TSTRIDE_B) + ka);
                ldm_x4(blf[p], blB + p * (16 * TSTRIDE_B) + ka);
            }
            // term-major: all HH, then HL, then LH
#pragma unroll
            for (int mf = 0; mf < 4; mf++)
#pragma unroll
                for (int nf = 0; nf < 4; nf++) {
                    const int p = nf >> 1, h = (nf & 1) * 2;
                    mma_bf16(acc[mf][nf], ahf[mf], bhf[p][h], bhf[p][h + 1]);
                }
#pragma unroll
            for (int mf = 0; mf < 4; mf++)
#pragma unroll
                for (int nf = 0; nf < 4; nf++) {
                    const int p = nf >> 1, h = (nf & 1) * 2;
                    mma_bf16(acc[mf][nf], ahf[mf], blf[p][h], blf[p][h + 1]);
                }
#pragma unroll
            for (int mf = 0; mf < 4; mf++)
#pragma unroll
                for (int nf = 0; nf < 4; nf++) {
                    const int p = nf >> 1, h = (nf & 1) * 2;
                    mma_bf16(acc[mf][nf], alf[mf], bhf[p][h], bhf[p][h + 1]);
                }
        }
        __syncthreads();
    }

    const int rr = lane >> 2;
    const int cc = (lane & 3) * 2;
#pragma unroll
    for (int mf = 0; mf < 4; mf++) {
#pragma unroll
        for (int nf = 0; nf < 4; nf++) {
            const size_t row = (size_t)(m0 + wm * 64 + mf * 16 + rr);
            const int col = n0 + wn * 32 + nf * 8 + cc;
            if (Hz) {
#pragma unroll
                for (int hh = 0; hh < 2; hh++) {
                    float a0 = acc[mf][nf][hh * 2 + 0];
                    float a1 = acc[mf][nf][hh * 2 + 1];
                    __nv_bfloat16 h0 = __float2bfloat16(a0);
                    __nv_bfloat16 h1 = __float2bfloat16(a1);
                    __nv_bfloat16 l0 = __float2bfloat16(a0 - __bfloat162float(h0));
                    __nv_bfloat16 l1 = __float2bfloat16(a1 - __bfloat162float(h1));
                    size_t off = (row + hh * 8) * D_MODEL + col;
                    *(__nv_bfloat162*)(Hz + off) = __nv_bfloat162(h0, h1);
                    *(__nv_bfloat162*)(Lz + off) = __nv_bfloat162(l0, l1);
                }
            } else {
                float* cp = Cf + row * D_MODEL + col;
                *(float2*)cp                 = make_float2(acc[mf][nf][0], acc[mf][nf][1]);
                *(float2*)(cp + 8 * D_MODEL) = make_float2(acc[mf][nf][2], acc[mf][nf][3]);
            }
        }
    }
}

// ================= HMMA flash attention (split-bf16, causal) =================
#define KSTR 144
#define QTILE_B  (128 * KSTR)
#define KVTILE_B (64 * KSTR)
#define KVSTAGE_B (4 * KVTILE_B)
#define FLASH_SMEM (2 * QTILE_B + 2 * KVSTAGE_B)   // 110592
#define SCL 0.18033688f                 // 0.125 * log2(e)

__global__ void __launch_bounds__(256, 1) flash_tc() {
    extern __shared__ char smf[];
    const uint32_t sb = smem_to_u32(smf);
    const uint32_t sQh = sb;
    const uint32_t sQl = sb + QTILE_B;
    const int tid  = threadIdx.x;
    const int wid  = tid >> 5;
    const int lane = tid & 31;
    const int qt = gridDim.x - 1 - blockIdx.x;    // heavy tiles first
    const int h  = blockIdx.y;
    const int b  = blockIdx.z;
    const int nkt = 2 * qt + 2;
    const size_t tok0 = (size_t)b * SEQ;

    for (int i = tid; i < 128 * 8; i += 256) {
        const int row = i >> 3, seg = i & 7;
        const size_t goff = (tok0 + qt * 128 + row) * D_MODEL + h * 64 + seg * 8;
        const uint32_t soff = row * KSTR + seg * 16;
        cp_async16(sQh + soff, g_qh + goff);
        cp_async16(sQl + soff, g_ql + goff);
    }
    auto kvbase = [&](int s) { return sb + 2 * QTILE_B + s * KVSTAGE_B; };
    auto loadKV = [&](int kt, int s) {
        const uint32_t base = kvbase(s);
        const int seg = tid & 7, r = tid >> 3;
        const int j0 = kt * 64;
#pragma unroll
        for (int rr2 = 0; rr2 < 2; rr2++) {
            const int row = r + rr2 * 32;
            const size_t goff = (tok0 + j0 + row) * D_MODEL + h * 64 + seg * 8;
            const uint32_t soff = row * KSTR + seg * 16;
            cp_async16(base + 0 * KVTILE_B + soff, g_kh + goff);
            cp_async16(base + 1 * KVTILE_B + soff, g_kl + goff);
            cp_async16(base + 2 * KVTILE_B + soff, g_vh + goff);
            cp_async16(base + 3 * KVTILE_B + soff, g_vl + goff);
        }
    };
    loadKV(0, 0);
    CP_COMMIT();
    CP_WAIT0();
    __syncthreads();

    uint32_t qhf[4][4], qlf[4][4];
    {
        const uint32_t aoff = (wid * 16 + (lane & 15)) * KSTR + (lane >> 4) * 16;
#pragma unroll
        for (int ka = 0; ka < 4; ka++) {
            ldm_x4(qhf[ka], sQh + aoff + ka * 32);
            ldm_x4(qlf[ka], sQl + aoff + ka * 32);
        }
    }

    float o[8][4];
#pragma unroll
    for (int f = 0; f < 8; f++)
#pragma unroll
        for (int k = 0; k < 4; k++) o[f][k] = 0.0f;
    float m0f = -1e30f, m1f = -1e30f, l0 = 0.0f, l1 = 0.0f;

    const int rmin = qt * 128 + wid * 16;
    const int g8 = lane >> 3;
    const uint32_t boffB = ((g8 >> 1) * 8 + (lane & 7)) * KSTR + (g8 & 1) * 16;
    const uint32_t voffB = (lane & 15) * KSTR + (lane >> 4) * 16;
    const int t2 = lane & 3, gq = lane >> 2;

    for (int kt = 0; kt < nkt; kt++) {
        const int s = kt & 1;
        if (kt + 1 < nkt) { loadKV(kt + 1, s ^ 1); CP_COMMIT(); }
        const uint32_t bK = kvbase(s);
        const int j0 = kt * 64;
        const bool activew = (j0 <= rmin + 15);

        if (activew) {
            float sacc[8][4];
#pragma unroll
            for (int f = 0; f < 8; f++)
#pragma unroll
                for (int k = 0; k < 4; k++) sacc[f][k] = 0.0f;

#pragma unroll
            for (int ka = 0; ka < 4; ka++) {
                uint32_t kbh[4][4], kbl[4][4];
#pragma unroll
                for (int nf16 = 0; nf16 < 4; nf16++) {
                    const uint32_t ad = bK + nf16 * (16 * KSTR) + boffB + ka * 32;
                    ldm_x4(kbh[nf16], ad);
                    ldm_x4(kbl[nf16], ad + KVTILE_B);
                }
#pragma unroll
                for (int nf16 = 0; nf16 < 4; nf16++)
#pragma unroll
                    for (int h2 = 0; h2 < 2; h2++)
                        mma_bf16(sacc[nf16 * 2 + h2], qhf[ka],
                                 kbh[nf16][h2 * 2], kbh[nf16][h2 * 2 + 1]);
#pragma unroll
                for (int nf16 = 0; nf16 < 4; nf16++)
#pragma unroll
                    for (int h2 = 0; h2 < 2; h2++)
                        mma_bf16(sacc[nf16 * 2 + h2], qhf[ka],
                                 kbl[nf16][h2 * 2], kbl[nf16][h2 * 2 + 1]);
#pragma unroll
                for (int nf16 = 0; nf16 < 4; nf16++)
#pragma unroll
                    for (int h2 = 0; h2 < 2; h2++)
                        mma_bf16(sacc[nf16 * 2 + h2], qlf[ka],
                                 kbh[nf16][h2 * 2], kbh[nf16][h2 * 2 + 1]);
            }

            const int row0 = rmin + gq, row1 = row0 + 8;
            if (j0 + 63 > rmin) {
#pragma unroll
                for (int f = 0; f < 8; f++) {
                    const int cbase = j0 + f * 8 + t2 * 2;
                    if (cbase     > row0) sacc[f][0] = -1e30f;
                    if (cbase + 1 > row0) sacc[f][1] = -1e30f;
                    if (cbase     > row1) sacc[f][2] = -1e30f;
                    if (cbase + 1 > row1) sacc[f][3] = -1e30f;
                }
            }

            float mx0 = -1e30f, mx1 = -1e30f;
#pragma unroll
            for (int f = 0; f < 8; f++) {
                mx0 = fmaxf(mx0, fmaxf(sacc[f][0], sacc[f][1]));
                mx1 = fmaxf(mx1, fmaxf(sacc[f][2], sacc[f][3]));
            }
#pragma unroll
            for (int off = 1; off < 4; off <<= 1) {
                mx0 = fmaxf(mx0, __shfl_xor_sync(0xffffffffu, mx0, off));
                mx1 = fmaxf(mx1, __shfl_xor_sync(0xffffffffu, mx1, off));
            }
            const float mn0 = fmaxf(m0f, mx0), mn1 = fmaxf(m1f, mx1);
            const float al0 = ex2f((m0f - mn0) * SCL);
            const float al1 = ex2f((m1f - mn1) * SCL);
            m0f = mn0; m1f = mn1;
            float sum0 = 0.0f, sum1 = 0.0f;
#pragma unroll
            for (int f = 0; f < 8; f++) {
                sacc[f][0] = ex2f((sacc[f][0] - mn0) * SCL);
                sacc[f][1] = ex2f((sacc[f][1] - mn0) * SCL);
                sacc[f][2] = ex2f((sacc[f][2] - mn1) * SCL);
                sacc[f][3] = ex2f((sacc[f][3] - mn1) * SCL);
                sum0 += sacc[f][0] + sacc[f][1];
                sum1 += sacc[f][2] + sacc[f][3];
            }
#pragma unroll
            for (int off = 1; off < 4; off <<= 1) {
                sum0 += __shfl_xor_sync(0xffffffffu, sum0, off);
                sum1 += __shfl_xor_sync(0xffffffffu, sum1, off);
            }
            l0 = l0 * al0 + sum0;
            l1 = l1 * al1 + sum1;
#pragma unroll
            for (int f = 0; f < 8; f++) {
                o[f][0] *= al0; o[f][1] *= al0;
                o[f][2] *= al1; o[f][3] *= al1;
            }

#pragma unroll
            for (int kj = 0; kj < 4; kj++) {
                uint32_t ph[4], pl[4];
                {
                    const float* pa = sacc[2 * kj];
                    const float* pb = sacc[2 * kj + 1];
                    float ra[4], rb[4];
#pragma unroll
                    for (int k = 0; k < 4; k++) {
                        ra[k] = pa[k] - __bfloat162float(__float2bfloat16(pa[k]));
                        rb[k] = pb[k] - __bfloat162float(__float2bfloat16(pb[k]));
                    }
                    ph[0] = pk_bf2(pa[0], pa[1]); ph[1] = pk_bf2(pa[2], pa[3]);
                    ph[2] = pk_bf2(pb[0], pb[1]); ph[3] = pk_bf2(pb[2], pb[3]);
                    pl[0] = pk_bf2(ra[0], ra[1]); pl[1] = pk_bf2(ra[2], ra[3]);
                    pl[2] = pk_bf2(rb[0], rb[1]); pl[3] = pk_bf2(rb[2], rb[3]);
                }
                uint32_t vbh[4][4], vbl[4][4];
#pragma unroll
                for (int nf16 = 0; nf16 < 4; nf16++) {
                    const uint32_t ad = bK + 2 * KVTILE_B + kj * (16 * KSTR) + voffB + nf16 * 32;
                    ldm_x4_trans(vbh[nf16], ad);
                    ldm_x4_trans(vbl[nf16], ad + KVTILE_B);
                }
#pragma unroll
                for (int nf16 = 0; nf16 < 4; nf16++)
#pragma unroll
                    for (int h2 = 0; h2 < 2; h2++)
                        mma_bf16(o[nf16 * 2 + h2], ph,
                                 vbh[nf16][h2 * 2], vbh[nf16][h2 * 2 + 1]);
#pragma unroll
                for (int nf16 = 0; nf16 < 4; nf16++)
#pragma unroll
                    for (int h2 = 0; h2 < 2; h2++)
                        mma_bf16(o[nf16 * 2 + h2], ph,
                                 vbl[nf16][h2 * 2], vbl[nf16][h2 * 2 + 1]);
#pragma unroll
                for (int nf16 = 0; nf16 < 4; nf16++)
#pragma unroll
                    for (int h2 = 0; h2 < 2; h2++)
                        mma_bf16(o[nf16 * 2 + h2], pl,
                                 vbh[nf16][h2 * 2], vbh[nf16][h2 * 2 + 1]);
            }
        }
        if (kt + 1 < nkt) CP_WAIT0();
        __syncthreads();
    }

    const float inv0 = 1.0f / l0, inv1 = 1.0f / l1;
    const size_t row0 = tok0 + qt * 128 + wid * 16 + gq;
#pragma unroll
    for (int f = 0; f < 8; f++) {
        const int col = h * 64 + f * 8 + t2 * 2;
        float a0 = o[f][0] * inv0, a1 = o[f][1] * inv0;
        float a2 = o[f][2] * inv1, a3 = o[f][3] * inv1;
        __nv_bfloat16 h0 = __float2bfloat16(a0), h1 = __float2bfloat16(a1);
        __nv_bfloat16 h2 = __float2bfloat16(a2), h3 = __float2bfloat16(a3);
        __nv_bfloat16 e0 = __float2bfloat16(a0 - __bfloat162float(h0));
        __nv_bfloat16 e1 = __float2bfloat16(a1 - __bfloat162float(h1));
        __nv_bfloat16 e2 = __float2bfloat16(a2 - __bfloat162float(h2));
        __nv_bfloat16 e3 = __float2bfloat16(a3 - __bfloat162float(h3));
        *(__nv_bfloat162*)(g_ch + row0 * D_MODEL + col)       = __nv_bfloat162(h0, h1);
        *(__nv_bfloat162*)(g_cl + row0 * D_MODEL + col)       = __nv_bfloat162(e0, e1);
        *(__nv_bfloat162*)(g_ch + (row0 + 8) * D_MODEL + col) = __nv_bfloat162(h2, h3);
        *(__nv_bfloat162*)(g_cl + (row0 + 8) * D_MODEL + col) = __nv_bfloat162(e2, e3);
    }
}

// ---------------- launch ----------------
extern "C" void kernel_launch(void* const* d_in, const int* in_sizes, int n_in,
                              void* d_out, int out_size) {
    (void)in_sizes; (void)n_in; (void)out_size;
    const float* x  = (const float*)d_in[0];
    const float* Wq = (const float*)d_in[1];
    const float* Wk = (const float*)d_in[2];
    const float* Wv = (const float*)d_in[3];
    const float* Wo = (const float*)d_in[4];
    float* out = (float*)d_out;

    __nv_bfloat16 *xh, *xl, *wh, *wl, *qh, *ql, *kh, *kl, *vh, *vl, *ch, *cl;
    cudaGetSymbolAddress((void**)&xh, g_xh);
    cudaGetSymbolAddress((void**)&xl, g_xl);
    cudaGetSymbolAddress((void**)&wh, g_wh);
    cudaGetSymbolAddress((void**)&wl, g_wl);
    cudaGetSymbolAddress((void**)&qh, g_qh);
    cudaGetSymbolAddress((void**)&ql, g_ql);
    cudaGetSymbolAddress((void**)&kh, g_kh);
    cudaGetSymbolAddress((void**)&kl, g_kl);
    cudaGetSymbolAddress((void**)&vh, g_vh);
    cudaGetSymbolAddress((void**)&vl, g_vl);
    cudaGetSymbolAddress((void**)&ch, g_ch);
    cudaGetSymbolAddress((void**)&cl, g_cl);

    cvt_all<<<dim3(M_TOT * D_MODEL / 4 / 256, 5), 256>>>(x, Wq, Wk, Wv, Wo);

    cudaFuncSetAttribute(gemm_tc, cudaFuncAttributeMaxDynamicSharedMemorySize, GEMM_SMEM);
    cudaFuncSetAttribute(flash_tc, cudaFuncAttributeMaxDynamicSharedMemorySize, FLASH_SMEM);

    gemm_tc<<<dim3(8, 32, 3), 256, GEMM_SMEM>>>(xh, xl, wh, wl, nullptr,
                                                qh, ql, kh, kl, vh, vl);
    flash_tc<<<dim3(SEQ / 128, NH, BATCH), 256, FLASH_SMEM>>>();
    gemm_tc<<<dim3(8, 32, 1), 256, GEMM_SMEM>>>(ch, cl, wh + 3 * MM, wl + 3 * MM, out,
                                                nullptr, nullptr, nullptr, nullptr,
                                                nullptr, nullptr);
}

// round 8
// speedup vs baseline: 4.3637x; 1.4274x over previous
#include <cuda_runtime.h>
#include <cuda_fp16.h>
#include <cstdint>
#include <math.h>

#define D_MODEL 1024
#define NH      16
#define DK      64
#define BATCH   2
#define SEQ     2048
#define M_TOT   (BATCH * SEQ)   // 4096
#define MM      (D_MODEL * D_MODEL)

// ---------------- scratch (static device memory; no allocations) ----------------
__device__ __half g_xh[M_TOT * D_MODEL];   // x split hi
__device__ __half g_xl[M_TOT * D_MODEL];   // x split lo
__device__ __half g_w [4 * MM];            // weights, single fp16
__device__ __half g_qh[M_TOT * D_MODEL];   // q split
__device__ __half g_ql[M_TOT * D_MODEL];
__device__ __half g_k [M_TOT * D_MODEL];   // k single
__device__ __half g_v [M_TOT * D_MODEL];   // v single
__device__ __half g_ch[M_TOT * D_MODEL];   // ctx split
__device__ __half g_cl[M_TOT * D_MODEL];

// ================= helpers =================
static __device__ __forceinline__ uint32_t smem_to_u32(const void* p) {
    uint32_t a;
    asm("{ .reg .u64 t; cvta.to.shared.u64 t, %1; cvt.u32.u64 %0, t; }" : "=r"(a) : "l"(p));
    return a;
}
static __device__ __forceinline__ void cp_async16(uint32_t saddr, const void* gaddr) {
    asm volatile("cp.async.cg.shared.global [%0], [%1], 16;" :: "r"(saddr), "l"(gaddr));
}
#define CP_COMMIT() asm volatile("cp.async.commit_group;" ::: "memory")
#define CP_WAIT0()  asm volatile("cp.async.wait_group 0;" ::: "memory")

static __device__ __forceinline__ void ldm_x4(uint32_t* r, uint32_t addr) {
    asm volatile("ldmatrix.sync.aligned.m8n8.x4.shared.b16 {%0,%1,%2,%3}, [%4];"
                 : "=r"(r[0]), "=r"(r[1]), "=r"(r[2]), "=r"(r[3]) : "r"(addr));
}
static __device__ __forceinline__ void ldm_x4_trans(uint32_t* r, uint32_t addr) {
    asm volatile("ldmatrix.sync.aligned.m8n8.x4.trans.shared.b16 {%0,%1,%2,%3}, [%4];"
                 : "=r"(r[0]), "=r"(r[1]), "=r"(r[2]), "=r"(r[3]) : "r"(addr));
}
static __device__ __forceinline__ void mma_f16(float* d, const uint32_t* a,
                                               uint32_t b0, uint32_t b1) {
    asm volatile(
        "mma.sync.aligned.m16n8k16.row.col.f32.f16.f16.f32 "
        "{%0,%1,%2,%3}, {%4,%5,%6,%7}, {%8,%9}, {%0,%1,%2,%3};"
        : "+f"(d[0]), "+f"(d[1]), "+f"(d[2]), "+f"(d[3])
        : "r"(a[0]), "r"(a[1]), "r"(a[2]), "r"(a[3]), "r"(b0), "r"(b1));
}
static __device__ __forceinline__ float ex2f(float x) {
    float r;
    asm("ex2.approx.ftz.f32 %0, %1;" : "=f"(r) : "f"(x));
    return r;
}
static __device__ __forceinline__ uint32_t pk_f16(float x, float y) {
    __half2 t = __floats2half2_rn(x, y);
    return *(uint32_t*)&t;
}

// ================= fused convert: W -> fp16 single; x -> fp16 split ==========
__global__ void __launch_bounds__(256) cvt_all(const float* __restrict__ x,
                                               const float* __restrict__ Wq,
                                               const float* __restrict__ Wk,
                                               const float* __restrict__ Wv,
                                               const float* __restrict__ Wo) {
    const int y = blockIdx.y;
    int i = (blockIdx.x * 256 + threadIdx.x) * 4;
    if (y < 4) {
        if (i >= MM) return;
        const float* src = (y == 0) ? Wq : (y == 1) ? Wk : (y == 2) ? Wv : Wo;
        __half* w = g_w + (size_t)y * MM;
        float4 v = *(const float4*)(src + i);
        *(__half2*)(w + i)     = __floats2half2_rn(v.x, v.y);
        *(__half2*)(w + i + 2) = __floats2half2_rn(v.z, v.w);
    } else {
        if (i >= M_TOT * D_MODEL) return;
        float4 v = *(const float4*)(x + i);
        __half h0 = __float2half_rn(v.x), h1 = __float2half_rn(v.y);
        __half h2 = __float2half_rn(v.z), h3 = __float2half_rn(v.w);
        *(__half2*)(g_xh + i)     = __half2(h0, h1);
        *(__half2*)(g_xh + i + 2) = __half2(h2, h3);
        *(__half2*)(g_xl + i) = __floats2half2_rn(v.x - __half2float(h0),
                                                  v.y - __half2float(h1));
        *(__half2*)(g_xl + i + 2) = __floats2half2_rn(v.z - __half2float(h2),
                                                      v.w - __half2float(h3));
    }
}

// ================= HMMA fp16 2-term GEMM =================
// C = (Ah+Al)[.,1024] * W[1024,1024]^T, 128x128 tiles, K-chunks 32, 2 CTAs/SM.
// 80B row stride: conflict-free ldmatrix/STS. 3 smem tiles/stage.
#define TSTRIDE_B 80
#define TILE_B    (128 * TSTRIDE_B)      // 10240
#define STAGE_B   (3 * TILE_B)           // 30720: Ah, Al, W
#define GEMM_SMEM (2 * STAGE_B)          // 61440
#define NCHUNK    32

__global__ void __launch_bounds__(256, 2)
gemm_tc(const __half* __restrict__ Ah, const __half* __restrict__ Al,
        const __half* __restrict__ W0,
        float* Cf,
        __half* H0, __half* L0,
        __half* H1, __half* L1,
        __half* H2, __half* L2) {
    extern __shared__ char smem[];
    const uint32_t sb = smem_to_u32(smem);
    const int tid  = threadIdx.x;
    const int wid  = tid >> 5;
    const int lane = tid & 31;
    const int z  = blockIdx.z;
    const int m0 = blockIdx.y * 128;
    const int n0 = blockIdx.x * 128;

    const __half* Wz = W0 + (size_t)z * MM;
    __half* Hz = (z == 0) ? H0 : (z == 1) ? H1 : H2;
    __half* Lz = (z == 0) ? L0 : (z == 1) ? L1 : L2;

    const int seg = tid & 3;
    const int r0  = tid >> 2;   // 0..63

    auto load_chunk = [&](int kc, int s) {
        const uint32_t sbase = sb + s * STAGE_B;
        const int ke = kc * 32 + seg * 8;
#pragma unroll
        for (int j = 0; j < 2; j++) {
            const int row = r0 + j * 64;
            const uint32_t soff = row * TSTRIDE_B + seg * 16;
            cp_async16(sbase + 0 * TILE_B + soff, Ah + (size_t)(m0 + row) * D_MODEL + ke);
            cp_async16(sbase + 1 * TILE_B + soff, Al + (size_t)(m0 + row) * D_MODEL + ke);
            cp_async16(sbase + 2 * TILE_B + soff, Wz + (size_t)(n0 + row) * D_MODEL + ke);
        }
    };

    const int wm = wid >> 2;
    const int wn = wid & 3;
    const uint32_t aRowOff = (uint32_t)((wm * 64 + (lane & 15)) * TSTRIDE_B + (lane >> 4) * 16);
    const int g = lane >> 3;
    const uint32_t bRowOff = (uint32_t)((wn * 32 + (g >> 1) * 8 + (lane & 7)) * TSTRIDE_B + (g & 1) * 16);

    float acc[4][4][4];
#pragma unroll
    for (int i = 0; i < 4; i++)
#pragma unroll
        for (int j = 0; j < 4; j++)
#pragma unroll
            for (int k = 0; k < 4; k++) acc[i][j][k] = 0.0f;

    load_chunk(0, 0);
    CP_COMMIT();

    for (int c = 0; c < NCHUNK; c++) {
        const int s = c & 1;
        CP_WAIT0();
        __syncthreads();
        if (c + 1 < NCHUNK) { load_chunk(c + 1, s ^ 1); CP_COMMIT(); }

        const uint32_t stage = sb + s * STAGE_B;
        const uint32_t ahB = stage + aRowOff;
        const uint32_t alB = ahB + TILE_B;
        const uint32_t wB  = stage + 2 * TILE_B + bRowOff;

#pragma unroll
        for (int kk = 0; kk < 2; kk++) {
            const uint32_t ka = kk * 32;
            uint32_t ahf[4][4], alf[4][4], whf[2][4];
#pragma unroll
            for (int mf = 0; mf < 4; mf++) {
                ldm_x4(ahf[mf], ahB + mf * (16 * TSTRIDE_B) + ka);
                ldm_x4(alf[mf], alB + mf * (16 * TSTRIDE_B) + ka);
            }
#pragma unroll
            for (int p = 0; p < 2; p++)
                ldm_x4(whf[p], wB + p * (16 * TSTRIDE_B) + ka);

#pragma unroll
            for (int mf = 0; mf < 4; mf++)
#pragma unroll
                for (int nf = 0; nf < 4; nf++) {
                    const int p = nf >> 1, h = (nf & 1) * 2;
                    mma_f16(acc[mf][nf], ahf[mf], whf[p][h], whf[p][h + 1]);
                }
#pragma unroll
            for (int mf = 0; mf < 4; mf++)
#pragma unroll
                for (int nf = 0; nf < 4; nf++) {
                    const int p = nf >> 1, h = (nf & 1) * 2;
                    mma_f16(acc[mf][nf], alf[mf], whf[p][h], whf[p][h + 1]);
                }
        }
        __syncthreads();
    }

    const int rr = lane >> 2;
    const int cc = (lane & 3) * 2;
#pragma unroll
    for (int mf = 0; mf < 4; mf++) {
#pragma unroll
        for (int nf = 0; nf < 4; nf++) {
            const size_t row = (size_t)(m0 + wm * 64 + mf * 16 + rr);
            const int col = n0 + wn * 32 + nf * 8 + cc;
            if (Cf) {
                float* cp = Cf + row * D_MODEL + col;
                *(float2*)cp                 = make_float2(acc[mf][nf][0], acc[mf][nf][1]);
                *(float2*)(cp + 8 * D_MODEL) = make_float2(acc[mf][nf][2], acc[mf][nf][3]);
            } else if (Lz) {   // split fp16 output (q)
#pragma unroll
                for (int hh = 0; hh < 2; hh++) {
                    float a0 = acc[mf][nf][hh * 2 + 0];
                    float a1 = acc[mf][nf][hh * 2 + 1];
                    __half h0 = __float2half_rn(a0);
                    __half h1 = __float2half_rn(a1);
                    size_t off = (row + hh * 8) * D_MODEL + col;
                    *(__half2*)(Hz + off) = __half2(h0, h1);
                    *(__half2*)(Lz + off) = __floats2half2_rn(a0 - __half2float(h0),
                                                              a1 - __half2float(h1));
                }
            } else {            // single fp16 output (k, v)
#pragma unroll
                for (int hh = 0; hh < 2; hh++) {
                    size_t off = (row + hh * 8) * D_MODEL + col;
                    *(__half2*)(Hz + off) = __floats2half2_rn(acc[mf][nf][hh * 2 + 0],
                                                              acc[mf][nf][hh * 2 + 1]);
                }
            }
        }
    }
}

// ================= HMMA flash attention (fp16 2-term, causal) =================
#define KSTR 144
#define QTILE_B  (128 * KSTR)
#define KVTILE_B (64 * KSTR)
#define KVSTAGE_B (2 * KVTILE_B)        // K, V (single each)
#define FLASH_SMEM (2 * QTILE_B + 2 * KVSTAGE_B)   // 73728
#define SCL 0.18033688f                 // 0.125 * log2(e)

__global__ void __launch_bounds__(256, 1) flash_tc() {
    extern __shared__ char smf[];
    const uint32_t sb = smem_to_u32(smf);
    const uint32_t sQh = sb;
    const uint32_t sQl = sb + QTILE_B;
    const int tid  = threadIdx.x;
    const int wid  = tid >> 5;
    const int lane = tid & 31;
    const int qt = gridDim.x - 1 - blockIdx.x;    // heavy tiles first
    const int h  = blockIdx.y;
    const int b  = blockIdx.z;
    const int nkt = 2 * qt + 2;
    const size_t tok0 = (size_t)b * SEQ;

    for (int i = tid; i < 128 * 8; i += 256) {
        const int row = i >> 3, seg = i & 7;
        const size_t goff = (tok0 + qt * 128 + row) * D_MODEL + h * 64 + seg * 8;
        const uint32_t soff = row * KSTR + seg * 16;
        cp_async16(sQh + soff, g_qh + goff);
        cp_async16(sQl + soff, g_ql + goff);
    }
    auto kvbase = [&](int s) { return sb + 2 * QTILE_B + s * KVSTAGE_B; };
    auto loadKV = [&](int kt, int s) {
        const uint32_t base = kvbase(s);
        const int seg = tid & 7, r = tid >> 3;
        const int j0 = kt * 64;
#pragma unroll
        for (int rr2 = 0; rr2 < 2; rr2++) {
            const int row = r + rr2 * 32;
            const size_t goff = (tok0 + j0 + row) * D_MODEL + h * 64 + seg * 8;
            const uint32_t soff = row * KSTR + seg * 16;
            cp_async16(base + 0 * KVTILE_B + soff, g_k + goff);
            cp_async16(base + 1 * KVTILE_B + soff, g_v + goff);
        }
    };
    loadKV(0, 0);
    CP_COMMIT();
    CP_WAIT0();
    __syncthreads();

    uint32_t qhf[4][4], qlf[4][4];
    {
        const uint32_t aoff = (wid * 16 + (lane & 15)) * KSTR + (lane >> 4) * 16;
#pragma unroll
        for (int ka = 0; ka < 4; ka++) {
            ldm_x4(qhf[ka], sQh + aoff + ka * 32);
            ldm_x4(qlf[ka], sQl + aoff + ka * 32);
        }
    }

    float o[8][4];
#pragma unroll
    for (int f = 0; f < 8; f++)
#pragma unroll
        for (int k = 0; k < 4; k++) o[f][k] = 0.0f;
    float m0f = -1e30f, m1f = -1e30f, l0 = 0.0f, l1 = 0.0f;

    const int rmin = qt * 128 + wid * 16;
    const int g8 = lane >> 3;
    const uint32_t boffB = ((g8 >> 1) * 8 + (lane & 7)) * KSTR + (g8 & 1) * 16;
    const uint32_t voffB = (lane & 15) * KSTR + (lane >> 4) * 16;
    const int t2 = lane & 3, gq = lane >> 2;

    for (int kt = 0; kt < nkt; kt++) {
        const int s = kt & 1;
        if (kt + 1 < nkt) { loadKV(kt + 1, s ^ 1); CP_COMMIT(); }
        const uint32_t bK = kvbase(s);
        const int j0 = kt * 64;
        const bool activew = (j0 <= rmin + 15);

        if (activew) {
            float sacc[8][4];
#pragma unroll
            for (int f = 0; f < 8; f++)
#pragma unroll
                for (int k = 0; k < 4; k++) sacc[f][k] = 0.0f;

            // ---- S = (Qh+Ql) K^T : 2 terms ----
#pragma unroll
            for (int ka = 0; ka < 4; ka++) {
                uint32_t kb[4][4];
#pragma unroll
                for (int nf16 = 0; nf16 < 4; nf16++)
                    ldm_x4(kb[nf16], bK + nf16 * (16 * KSTR) + boffB + ka * 32);
#pragma unroll
                for (int nf16 = 0; nf16 < 4; nf16++)
#pragma unroll
                    for (int h2 = 0; h2 < 2; h2++)
                        mma_f16(sacc[nf16 * 2 + h2], qhf[ka],
                                kb[nf16][h2 * 2], kb[nf16][h2 * 2 + 1]);
#pragma unroll
                for (int nf16 = 0; nf16 < 4; nf16++)
#pragma unroll
                    for (int h2 = 0; h2 < 2; h2++)
                        mma_f16(sacc[nf16 * 2 + h2], qlf[ka],
                                kb[nf16][h2 * 2], kb[nf16][h2 * 2 + 1]);
            }

            // ---- causal mask (diagonal tiles only) ----
            const int row0 = rmin + gq, row1 = row0 + 8;
            if (j0 + 63 > rmin) {
#pragma unroll
                for (int f = 0; f < 8; f++) {
                    const int cbase = j0 + f * 8 + t2 * 2;
                    if (cbase     > row0) sacc[f][0] = -1e30f;
                    if (cbase + 1 > row0) sacc[f][1] = -1e30f;
                    if (cbase     > row1) sacc[f][2] = -1e30f;
                    if (cbase + 1 > row1) sacc[f][3] = -1e30f;
                }
            }

            // ---- online softmax (rows gq, gq+8) ----
            float mx0 = -1e30f, mx1 = -1e30f;
#pragma unroll
            for (int f = 0; f < 8; f++) {
                mx0 = fmaxf(mx0, fmaxf(sacc[f][0], sacc[f][1]));
                mx1 = fmaxf(mx1, fmaxf(sacc[f][2], sacc[f][3]));
            }
#pragma unroll
            for (int off = 1; off < 4; off <<= 1) {
                mx0 = fmaxf(mx0, __shfl_xor_sync(0xffffffffu, mx0, off));
                mx1 = fmaxf(mx1, __shfl_xor_sync(0xffffffffu, mx1, off));
            }
            const float mn0 = fmaxf(m0f, mx0), mn1 = fmaxf(m1f, mx1);
            const float al0 = ex2f((m0f - mn0) * SCL);
            const float al1 = ex2f((m1f - mn1) * SCL);
            m0f = mn0; m1f = mn1;
            float sum0 = 0.0f, sum1 = 0.0f;
#pragma unroll
            for (int f = 0; f < 8; f++) {
                sacc[f][0] = ex2f((sacc[f][0] - mn0) * SCL);
                sacc[f][1] = ex2f((sacc[f][1] - mn0) * SCL);
                sacc[f][2] = ex2f((sacc[f][2] - mn1) * SCL);
                sacc[f][3] = ex2f((sacc[f][3] - mn1) * SCL);
                sum0 += sacc[f][0] + sacc[f][1];
                sum1 += sacc[f][2] + sacc[f][3];
            }
#pragma unroll
            for (int off = 1; off < 4; off <<= 1) {
                sum0 += __shfl_xor_sync(0xffffffffu, sum0, off);
                sum1 += __shfl_xor_sync(0xffffffffu, sum1, off);
            }
            l0 = l0 * al0 + sum0;
            l1 = l1 * al1 + sum1;
#pragma unroll
            for (int f = 0; f < 8; f++) {
                o[f][0] *= al0; o[f][1] *= al0;
                o[f][2] *= al1; o[f][3] *= al1;
            }

            // ---- O += (Ph+Pl) V : 2 terms ----
#pragma unroll
            for (int kj = 0; kj < 4; kj++) {
                uint32_t ph[4], pl[4];
                {
                    const float* pa = sacc[2 * kj];
                    const float* pb = sacc[2 * kj + 1];
                    float ra[4], rb[4];
#pragma unroll
                    for (int k = 0; k < 4; k++) {
                        ra[k] = pa[k] - __half2float(__float2half_rn(pa[k]));
                        rb[k] = pb[k] - __half2float(__float2half_rn(pb[k]));
                    }
                    ph[0] = pk_f16(pa[0], pa[1]); ph[1] = pk_f16(pa[2], pa[3]);
                    ph[2] = pk_f16(pb[0], pb[1]); ph[3] = pk_f16(pb[2], pb[3]);
                    pl[0] = pk_f16(ra[0], ra[1]); pl[1] = pk_f16(ra[2], ra[3]);
                    pl[2] = pk_f16(rb[0], rb[1]); pl[3] = pk_f16(rb[2], rb[3]);
                }
                uint32_t vb[4][4];
#pragma unroll
                for (int nf16 = 0; nf16 < 4; nf16++)
                    ldm_x4_trans(vb[nf16],
                                 bK + KVTILE_B + kj * (16 * KSTR) + voffB + nf16 * 32);
#pragma unroll
                for (int nf16 = 0; nf16 < 4; nf16++)
#pragma unroll
                    for (int h2 = 0; h2 < 2; h2++)
                        mma_f16(o[nf16 * 2 + h2], ph,
                                vb[nf16][h2 * 2], vb[nf16][h2 * 2 + 1]);
#pragma unroll
                for (int nf16 = 0; nf16 < 4; nf16++)
#pragma unroll
                    for (int h2 = 0; h2 < 2; h2++)
                        mma_f16(o[nf16 * 2 + h2], pl,
                                vb[nf16][h2 * 2], vb[nf16][h2 * 2 + 1]);
            }
        }
        if (kt + 1 < nkt) CP_WAIT0();
        __syncthreads();
    }

    // ---- normalize + split-fp16 store of ctx ----
    const float inv0 = 1.0f / l0, inv1 = 1.0f / l1;
    const size_t row0 = tok0 + qt * 128 + wid * 16 + gq;
#pragma unroll
    for (int f = 0; f < 8; f++) {
        const int col = h * 64 + f * 8 + t2 * 2;
        float a0 = o[f][0] * inv0, a1 = o[f][1] * inv0;
        float a2 = o[f][2] * inv1, a3 = o[f][3] * inv1;
        __half h0 = __float2half_rn(a0), h1 = __float2half_rn(a1);
        __half h2 = __float2half_rn(a2), h3 = __float2half_rn(a3);
        *(__half2*)(g_ch + row0 * D_MODEL + col)       = __half2(h0, h1);
        *(__half2*)(g_cl + row0 * D_MODEL + col)       =
            __floats2half2_rn(a0 - __half2float(h0), a1 - __half2float(h1));
        *(__half2*)(g_ch + (row0 + 8) * D_MODEL + col) = __half2(h2, h3);
        *(__half2*)(g_cl + (row0 + 8) * D_MODEL + col) =
            __floats2half2_rn(a2 - __half2float(h2), a3 - __half2float(h3));
    }
}

// ---------------- launch ----------------
extern "C" void kernel_launch(void* const* d_in, const int* in_sizes, int n_in,
                              void* d_out, int out_size) {
    (void)in_sizes; (void)n_in; (void)out_size;
    const float* x  = (const float*)d_in[0];
    const float* Wq = (const float*)d_in[1];
    const float* Wk = (const float*)d_in[2];
    const float* Wv = (const float*)d_in[3];
    const float* Wo = (const float*)d_in[4];
    float* out = (float*)d_out;

    __half *xh, *xl, *w, *qh, *ql, *k, *v, *ch, *cl;
    cudaGetSymbolAddress((void**)&xh, g_xh);
    cudaGetSymbolAddress((void**)&xl, g_xl);
    cudaGetSymbolAddress((void**)&w,  g_w);
    cudaGetSymbolAddress((void**)&qh, g_qh);
    cudaGetSymbolAddress((void**)&ql, g_ql);
    cudaGetSymbolAddress((void**)&k,  g_k);
    cudaGetSymbolAddress((void**)&v,  g_v);
    cudaGetSymbolAddress((void**)&ch, g_ch);
    cudaGetSymbolAddress((void**)&cl, g_cl);

    cvt_all<<<dim3(M_TOT * D_MODEL / 4 / 256, 5), 256>>>(x, Wq, Wk, Wv, Wo);

    cudaFuncSetAttribute(gemm_tc, cudaFuncAttributeMaxDynamicSharedMemorySize, GEMM_SMEM);
    cudaFuncSetAttribute(flash_tc, cudaFuncAttributeMaxDynamicSharedMemorySize, FLASH_SMEM);

    // QKV: z=0 -> q (split), z=1 -> k (single), z=2 -> v (single)
    gemm_tc<<<dim3(8, 32, 3), 256, GEMM_SMEM>>>(xh, xl, w, nullptr,
                                                qh, ql, k, nullptr, v, nullptr);
    flash_tc<<<dim3(SEQ / 128, NH, BATCH), 256, FLASH_SMEM>>>();
    // out projection: ctx split x Wo single -> fp32 out
    gemm_tc<<<dim3(8, 32, 1), 256, GEMM_SMEM>>>(ch, cl, w + 3 * MM, out,
                                                nullptr, nullptr, nullptr, nullptr,
                                                nullptr, nullptr);
}